// round 10
// baseline (speedup 1.0000x reference)
#include <cuda_runtime.h>
#include <cuda_bf16.h>

#define BD      2
#define SEQ     2048
#define DM      768
#define NH      12
#define DK      64
#define MROWS   (BD*SEQ)
#define ATT_SCALE 0.125f

typedef __nv_bfloat16 bf16;

// ===========================================================================
// helpers
// ===========================================================================
__device__ __forceinline__ unsigned smem_u32(const void* p) {
    unsigned a;
    asm("{ .reg .u64 t; cvta.to.shared.u64 t, %1; cvt.u32.u64 %0, t; }"
        : "=r"(a) : "l"(p));
    return a;
}
__device__ __forceinline__ void ldsm4(unsigned& r0, unsigned& r1, unsigned& r2,
                                      unsigned& r3, unsigned a) {
    asm volatile("ldmatrix.sync.aligned.m8n8.x4.shared.b16 {%0,%1,%2,%3}, [%4];"
        : "=r"(r0), "=r"(r1), "=r"(r2), "=r"(r3) : "r"(a));
}
__device__ __forceinline__ void ldsm4t(unsigned& r0, unsigned& r1, unsigned& r2,
                                       unsigned& r3, unsigned a) {
    asm volatile("ldmatrix.sync.aligned.m8n8.x4.trans.shared.b16 {%0,%1,%2,%3}, [%4];"
        : "=r"(r0), "=r"(r1), "=r"(r2), "=r"(r3) : "r"(a));
}
__device__ __forceinline__ void mma_bf16(float* c, const unsigned* a,
                                         unsigned b0, unsigned b1) {
    asm volatile("mma.sync.aligned.m16n8k16.row.col.f32.bf16.bf16.f32 "
        "{%0,%1,%2,%3},{%4,%5,%6,%7},{%8,%9},{%0,%1,%2,%3};"
        : "+f"(c[0]), "+f"(c[1]), "+f"(c[2]), "+f"(c[3])
        : "r"(a[0]), "r"(a[1]), "r"(a[2]), "r"(a[3]), "r"(b0), "r"(b1));
}
__device__ __forceinline__ unsigned pack_hilo(float x, float y, unsigned& lo) {
    bf16 hx = __float2bfloat16(x), hy = __float2bfloat16(y);
    bf16 lx = __float2bfloat16(x - __bfloat162float(hx));
    bf16 ly = __float2bfloat16(y - __bfloat162float(hy));
    lo = (unsigned)__bfloat16_as_ushort(lx) | ((unsigned)__bfloat16_as_ushort(ly) << 16);
    return (unsigned)__bfloat16_as_ushort(hx) | ((unsigned)__bfloat16_as_ushort(hy) << 16);
}
#define CPA16(d, s) \
    asm volatile("cp.async.cg.shared.global [%0], [%1], 16;" :: "r"(d), "l"(s) : "memory")
#define CP_COMMIT() asm volatile("cp.async.commit_group;" ::: "memory")
#define CP_WAIT1()  asm volatile("cp.async.wait_group 1;" ::: "memory")
#define CP_WAIT0()  asm volatile("cp.async.wait_group 0;" ::: "memory")

// ===========================================================================
// scratch
// ===========================================================================
__device__ bf16 g_xhi[MROWS*DM], g_xlo[MROWS*DM];
__device__ bf16 g_Whi[4*DM*DM],  g_Wlo[4*DM*DM];     // Wq, Wk, Wv, Wf
__device__ bf16 g_WoThi[DM*DM],  g_WoTlo[DM*DM];
__device__ bf16 g_Wchi[DM*DM],   g_Wclo[DM*DM];      // Wc = Wf @ Wo
__device__ bf16 g_Qhi[MROWS*DM], g_Qlo[MROWS*DM];
__device__ bf16 g_Khi[MROWS*DM], g_Klo[MROWS*DM];
__device__ bf16 g_Vhi[MROWS*DM], g_Vlo[MROWS*DM];
__device__ bf16 g_Mhi[MROWS*DM], g_Mlo[MROWS*DM];
__device__ float g_bp[DM];
__device__ float g_zb[DM];

// ===========================================================================
// merged fp32 -> bf16 hi/lo splitter
// ===========================================================================
#define N4X (MROWS*DM/4)
#define N4W (DM*DM/4)
__global__ void __launch_bounds__(256) cvt_all(
    const float* __restrict__ x,
    const float* __restrict__ Wq, const float* __restrict__ Wk,
    const float* __restrict__ Wv, const float* __restrict__ Wf,
    bf16* __restrict__ xhi, bf16* __restrict__ xlo,
    bf16* __restrict__ Whi, bf16* __restrict__ Wlo)
{
    int i = blockIdx.x * blockDim.x + threadIdx.x;
    const float* src; bf16 *hi, *lo; int off;
    if (i < N4X) { src = x; hi = xhi; lo = xlo; off = i; }
    else {
        int j = i - N4X;
        if (j >= 4 * N4W) return;
        int w = j / N4W;
        off = j - w * N4W;
        src = (w == 0) ? Wq : (w == 1) ? Wk : (w == 2) ? Wv : Wf;
        hi = Whi + (size_t)w * (DM*DM);
        lo = Wlo + (size_t)w * (DM*DM);
    }
    float4 v = reinterpret_cast<const float4*>(src)[off];
    uint2 hp, lp;
    hp.x = pack_hilo(v.x, v.y, lp.x);
    hp.y = pack_hilo(v.z, v.w, lp.y);
    reinterpret_cast<uint2*>(hi)[off] = hp;
    reinterpret_cast<uint2*>(lo)[off] = lp;
}

// ===========================================================================
// Wo transpose + split
// ===========================================================================
__global__ void __launch_bounds__(256) trans_wo(
    const float* __restrict__ Wo, bf16* __restrict__ hi, bf16* __restrict__ lo)
{
    __shared__ float t[32][33];
    int bx = blockIdx.x * 32, by = blockIdx.y * 32;
    int tx = threadIdx.x & 31, ty = threadIdx.x >> 5;
    #pragma unroll
    for (int i = 0; i < 32; i += 8)
        t[ty + i][tx] = Wo[(size_t)(by + ty + i) * DM + bx + tx];
    __syncthreads();
    #pragma unroll
    for (int i = 0; i < 32; i += 8) {
        float v = t[tx][ty + i];
        bf16 h = __float2bfloat16(v);
        bf16 l = __float2bfloat16(v - __bfloat162float(h));
        size_t o = (size_t)(bx + ty + i) * DM + by + tx;
        hi[o] = h;
        lo[o] = l;
    }
}

// ===========================================================================
// b' = Wf @ bo + bf
// ===========================================================================
__global__ void __launch_bounds__(256) bprime_k(
    const float* __restrict__ Wf, const float* __restrict__ bo,
    const float* __restrict__ bfv, float* __restrict__ bp)
{
    int n = blockIdx.x * 8 + (threadIdx.x >> 5);
    int lane = threadIdx.x & 31;
    if (n >= DM) return;
    float s = 0.0f;
    for (int j = lane; j < DM; j += 32) s += Wf[(size_t)n * DM + j] * bo[j];
    #pragma unroll
    for (int o = 16; o > 0; o >>= 1) s += __shfl_xor_sync(0xffffffffu, s, o);
    if (lane == 0) bp[n] = s + bfv[n];
}

// ===========================================================================
// GEMM v2: C[M,768] = A @ W^T + bias (split-bf16 3-pass)
// CTA tile 128x128, K-chunk 32, cp.async 2-stage (40KB/stage -> 2 CTA/SM).
// 8 warps as 2(M) x 4(N), warp tile 64x32 -> 32 FLOP/smem-byte.
// ===========================================================================
#define GLD 40                       // padded K-row stride in bf16 (80 B)
#define G_T   (128*GLD*2)            // 10240 B per tile
#define G_AH  0
#define G_AL  (1*G_T)
#define G_BH  (2*G_T)
#define G_BL  (3*G_T)
#define G_STAGE (4*G_T)              // 40960 B
#define GEMM_SMEM (2*G_STAGE)        // 81920 B

__device__ __forceinline__ void gemm_core(
    const bf16* __restrict__ Ahi, const bf16* __restrict__ Alo,
    const bf16* __restrict__ Bhi, const bf16* __restrict__ Blo,
    const float* __restrict__ bias,
    float* __restrict__ Cf, bf16* __restrict__ Chi, bf16* __restrict__ Clo)
{
    extern __shared__ char smc[];
    const int tid = threadIdx.x, lane = tid & 31, wid = tid >> 5;
    const int wm = wid >> 2, wn = wid & 3;      // 2 x 4 warps
    const int row0 = blockIdx.y * 128, col0 = blockIdx.x * 128;
    const unsigned sb = smem_u32(smc);

    float acc[4][4][4];                          // mi(4 x m16) x no(4 x n8)
    #pragma unroll
    for (int i = 0; i < 4; i++)
        #pragma unroll
        for (int j = 0; j < 4; j++)
            #pragma unroll
            for (int k = 0; k < 4; k++) acc[i][j][k] = 0.0f;

    auto issue = [&](int s, int kc) {
        unsigned stg = sb + s * G_STAGE;
        #pragma unroll
        for (int u = 0; u < 2; u++) {
            int idx = u * 256 + tid;             // 512 x 16B per tile
            int r = idx >> 2, c = idx & 3;
            unsigned d = (unsigned)(r * GLD + c * 8) * 2;
            CPA16(stg + G_AH + d, (const char*)(Ahi + (size_t)(row0 + r) * DM + kc) + c * 16);
            CPA16(stg + G_AL + d, (const char*)(Alo + (size_t)(row0 + r) * DM + kc) + c * 16);
            CPA16(stg + G_BH + d, (const char*)(Bhi + (size_t)(col0 + r) * DM + kc) + c * 16);
            CPA16(stg + G_BL + d, (const char*)(Blo + (size_t)(col0 + r) * DM + kc) + c * 16);
        }
    };

    issue(0, 0);
    CP_COMMIT();

    const int NC = DM / 32;   // 24
    for (int c = 0; c < NC; c++) {
        const int p = c & 1;
        CP_WAIT0();
        __syncthreads();
        if (c + 1 < NC) { issue(p ^ 1, (c + 1) * 32); CP_COMMIT(); }

        const unsigned stg = sb + p * G_STAGE;
        #pragma unroll
        for (int ks = 0; ks < 2; ks++) {
            const int kr = ks * 16;
            // B fragments for this warp's 32 columns (2 x n16, hi+lo)
            unsigned bh[2][4], bl[2][4];
            #pragma unroll
            for (int ni2 = 0; ni2 < 2; ni2++) {
                int n = wn * 32 + ni2 * 16 + (lane >> 4) * 8 + (lane & 7);
                int kk = kr + ((lane >> 3) & 1) * 8;
                ldsm4(bh[ni2][0], bh[ni2][1], bh[ni2][2], bh[ni2][3],
                      stg + G_BH + (n * GLD + kk) * 2);
                ldsm4(bl[ni2][0], bl[ni2][1], bl[ni2][2], bl[ni2][3],
                      stg + G_BL + (n * GLD + kk) * 2);
            }
            // A fragments in two halves of 2 x m16 each (register pressure)
            #pragma unroll
            for (int hm = 0; hm < 2; hm++) {
                unsigned ah[2][4], al[2][4];
                #pragma unroll
                for (int mi2 = 0; mi2 < 2; mi2++) {
                    int m = wm * 64 + (hm * 2 + mi2) * 16 + (lane & 15);
                    int kk = kr + (lane >> 4) * 8;
                    ldsm4(ah[mi2][0], ah[mi2][1], ah[mi2][2], ah[mi2][3],
                          stg + G_AH + (m * GLD + kk) * 2);
                    ldsm4(al[mi2][0], al[mi2][1], al[mi2][2], al[mi2][3],
                          stg + G_AL + (m * GLD + kk) * 2);
                }
                #pragma unroll
                for (int mi2 = 0; mi2 < 2; mi2++)
                    #pragma unroll
                    for (int no = 0; no < 4; no++) {
                        unsigned* bhp = &bh[no >> 1][(no & 1) * 2];
                        unsigned* blp = &bl[no >> 1][(no & 1) * 2];
                        float* a = acc[hm * 2 + mi2][no];
                        mma_bf16(a, ah[mi2], bhp[0], bhp[1]);
                        mma_bf16(a, ah[mi2], blp[0], blp[1]);
                        mma_bf16(a, al[mi2], bhp[0], bhp[1]);
                    }
            }
        }
    }

    #pragma unroll
    for (int mi = 0; mi < 4; mi++)
        #pragma unroll
        for (int ni = 0; ni < 4; ni++) {
            int row = row0 + wm * 64 + mi * 16 + (lane >> 2);
            int col = col0 + wn * 32 + ni * 8 + (lane & 3) * 2;
            float2 bv = *reinterpret_cast<const float2*>(&bias[col]);
            #pragma unroll
            for (int h = 0; h < 2; h++) {
                int r = row + h * 8;
                float vx = acc[mi][ni][h * 2 + 0] + bv.x;
                float vy = acc[mi][ni][h * 2 + 1] + bv.y;
                size_t off = (size_t)r * DM + col;
                if (Cf) *reinterpret_cast<float2*>(&Cf[off]) = make_float2(vx, vy);
                if (Chi) {
                    unsigned lo, hi = pack_hilo(vx, vy, lo);
                    *reinterpret_cast<unsigned*>(&Chi[off]) = hi;
                    *reinterpret_cast<unsigned*>(&Clo[off]) = lo;
                }
            }
        }
}

__global__ void __launch_bounds__(256, 2) mma_gemm(
    const bf16* __restrict__ Ahi, const bf16* __restrict__ Alo,
    const bf16* __restrict__ Bhi, const bf16* __restrict__ Blo,
    const float* __restrict__ bias,
    float* __restrict__ Cf, bf16* __restrict__ Chi, bf16* __restrict__ Clo)
{
    gemm_core(Ahi, Alo, Bhi, Blo, bias, Cf, Chi, Clo);
}

__global__ void __launch_bounds__(256, 2) qkv_gemm(
    const bf16* __restrict__ xhi, const bf16* __restrict__ xlo,
    const bf16* __restrict__ Whi, const bf16* __restrict__ Wlo,
    const float* __restrict__ bq, const float* __restrict__ bk,
    const float* __restrict__ bv,
    bf16* __restrict__ Qhi, bf16* __restrict__ Qlo,
    bf16* __restrict__ Khi, bf16* __restrict__ Klo,
    bf16* __restrict__ Vhi, bf16* __restrict__ Vlo)
{
    const int z = blockIdx.z;
    const int WN = DM * DM;
    const float* bias = (z == 0) ? bq : (z == 1) ? bk : bv;
    bf16* Chi = (z == 0) ? Qhi : (z == 1) ? Khi : Vhi;
    bf16* Clo = (z == 0) ? Qlo : (z == 1) ? Klo : Vlo;
    gemm_core(xhi, xlo, Whi + (size_t)z * WN, Wlo + (size_t)z * WN, bias,
              nullptr, Chi, Clo);
}

// ===========================================================================
// Attention (round-8 proven config): 128 Q-rows/block, 8 warps, S register-
// resident, 3-stage cp.async K/V pipeline.
// ===========================================================================
#define ALD 72
#define A_QH_B 0
#define A_QL_B 18432
#define A_STG_B 36864
#define A_STG_SZ 36864
#define A_KH_B 0
#define A_KL_B 9216
#define A_VH_B 18432
#define A_VL_B 27648
#define ATTN_SMEM (36864 + 3*A_STG_SZ)   // 147456
#define OLD 66

__global__ void __launch_bounds__(256) attn_mma(
    const bf16* __restrict__ Qhi, const bf16* __restrict__ Qlo,
    const bf16* __restrict__ Khi, const bf16* __restrict__ Klo,
    const bf16* __restrict__ Vhi, const bf16* __restrict__ Vlo,
    bf16* __restrict__ Mhi, bf16* __restrict__ Mlo)
{
    extern __shared__ char sma[];
    const int tid = threadIdx.x, lane = tid & 31, wid = tid >> 5;
    const int wm = wid >> 1, wn = wid & 1;
    const int bh = blockIdx.y;
    const int s0 = blockIdx.x * 128;
    const size_t base = (size_t)bh * SEQ * DK;
    const unsigned sb = smem_u32(sma);

    #pragma unroll
    for (int u = 0; u < 4; u++) {
        int idx = u * 256 + tid;
        int r = idx >> 3, c = idx & 7;
        size_t g = base + (size_t)(s0 + r) * DK + c * 8;
        *reinterpret_cast<uint4*>(sma + A_QH_B + (r * ALD + c * 8) * 2) =
            *reinterpret_cast<const uint4*>(Qhi + g);
        *reinterpret_cast<uint4*>(sma + A_QL_B + (r * ALD + c * 8) * 2) =
            *reinterpret_cast<const uint4*>(Qlo + g);
    }

    auto issue = [&](int s, int t0) {
        unsigned stg = sb + A_STG_B + s * A_STG_SZ;
        #pragma unroll
        for (int u = 0; u < 2; u++) {
            int idx = u * 256 + tid;
            int r = idx >> 3, c = idx & 7;
            size_t g = (base + (size_t)(t0 + r) * DK) * 2 + c * 16;
            unsigned d = (unsigned)(r * ALD + c * 8) * 2;
            CPA16(stg + A_KH_B + d, (const char*)Khi + g);
            CPA16(stg + A_KL_B + d, (const char*)Klo + g);
            CPA16(stg + A_VH_B + d, (const char*)Vhi + g);
            CPA16(stg + A_VL_B + d, (const char*)Vlo + g);
        }
    };

    float oacc[2][8][4];
    #pragma unroll
    for (int i = 0; i < 2; i++)
        #pragma unroll
        for (int j = 0; j < 8; j++)
            #pragma unroll
            for (int k = 0; k < 4; k++) oacc[i][j][k] = 0.0f;

    issue(0, 0);
    CP_COMMIT();
    issue(1, 64);
    CP_COMMIT();

    const int NC = SEQ / 64;   // 32
    int p = 0;
    for (int c = 0; c < NC; c++) {
        if (c + 1 < NC) { CP_WAIT1(); }
        else            { CP_WAIT0(); }
        __syncthreads();
        if (c + 2 < NC) { issue((p + 2) % 3, (c + 2) * 64); CP_COMMIT(); }

        const unsigned stg = sb + A_STG_B + p * A_STG_SZ;

        float sacc[2][4][4];
        #pragma unroll
        for (int i = 0; i < 2; i++)
            #pragma unroll
            for (int j = 0; j < 4; j++)
                #pragma unroll
                for (int k = 0; k < 4; k++) sacc[i][j][k] = 0.0f;

        #pragma unroll
        for (int ks = 0; ks < 4; ks++) {
            const int kr = ks * 16;
            unsigned ah[2][4], al[2][4], bh_[2][4], bl_[2][4];
            #pragma unroll
            for (int mi = 0; mi < 2; mi++) {
                int m = wm * 32 + mi * 16 + (lane & 15);
                int kk = kr + (lane >> 4) * 8;
                ldsm4(ah[mi][0], ah[mi][1], ah[mi][2], ah[mi][3],
                      sb + A_QH_B + (m * ALD + kk) * 2);
                ldsm4(al[mi][0], al[mi][1], al[mi][2], al[mi][3],
                      sb + A_QL_B + (m * ALD + kk) * 2);
            }
            #pragma unroll
            for (int ni2 = 0; ni2 < 2; ni2++) {
                int n = wn * 32 + ni2 * 16 + (lane >> 4) * 8 + (lane & 7);
                int kk = kr + ((lane >> 3) & 1) * 8;
                ldsm4(bh_[ni2][0], bh_[ni2][1], bh_[ni2][2], bh_[ni2][3],
                      stg + A_KH_B + (n * ALD + kk) * 2);
                ldsm4(bl_[ni2][0], bl_[ni2][1], bl_[ni2][2], bl_[ni2][3],
                      stg + A_KL_B + (n * ALD + kk) * 2);
            }
            #pragma unroll
            for (int mi = 0; mi < 2; mi++)
                #pragma unroll
                for (int ni = 0; ni < 4; ni++) {
                    unsigned* bhp = &bh_[ni >> 1][(ni & 1) * 2];
                    unsigned* blp = &bl_[ni >> 1][(ni & 1) * 2];
                    mma_bf16(sacc[mi][ni], ah[mi], bhp[0], bhp[1]);
                    mma_bf16(sacc[mi][ni], ah[mi], blp[0], blp[1]);
                    mma_bf16(sacc[mi][ni], al[mi], bhp[0], bhp[1]);
                }
        }

        #pragma unroll
        for (int j = 0; j < 2; j++) {
            unsigned sa_h[2][4], sa_l[2][4];
            #pragma unroll
            for (int mi = 0; mi < 2; mi++) {
                float* t0 = sacc[mi][2*j];
                float* t1 = sacc[mi][2*j + 1];
                sa_h[mi][0] = pack_hilo(t0[0]*ATT_SCALE, t0[1]*ATT_SCALE, sa_l[mi][0]);
                sa_h[mi][1] = pack_hilo(t0[2]*ATT_SCALE, t0[3]*ATT_SCALE, sa_l[mi][1]);
                sa_h[mi][2] = pack_hilo(t1[0]*ATT_SCALE, t1[1]*ATT_SCALE, sa_l[mi][2]);
                sa_h[mi][3] = pack_hilo(t1[2]*ATT_SCALE, t1[3]*ATT_SCALE, sa_l[mi][3]);
            }
            int kk = wn * 32 + j * 16 + (lane & 7) + ((lane >> 3) & 1) * 8;
            unsigned vh[4][4], vl[4][4];
            #pragma unroll
            for (int no2 = 0; no2 < 4; no2++) {
                int n = no2 * 16 + (lane >> 4) * 8;
                ldsm4t(vh[no2][0], vh[no2][1], vh[no2][2], vh[no2][3],
                       stg + A_VH_B + (kk * ALD + n) * 2);
                ldsm4t(vl[no2][0], vl[no2][1], vl[no2][2], vl[no2][3],
                       stg + A_VL_B + (kk * ALD + n) * 2);
            }
            #pragma unroll
            for (int mi = 0; mi < 2; mi++)
                #pragma unroll
                for (int no = 0; no < 8; no++) {
                    unsigned* bhp = &vh[no >> 1][(no & 1) * 2];
                    unsigned* blp = &vl[no >> 1][(no & 1) * 2];
                    mma_bf16(oacc[mi][no], sa_h[mi], bhp[0], bhp[1]);
                    mma_bf16(oacc[mi][no], sa_h[mi], blp[0], blp[1]);
                    mma_bf16(oacc[mi][no], sa_l[mi], bhp[0], bhp[1]);
                }
        }
        p = (p + 1) % 3;
    }

    __syncthreads();
    float* sOb = reinterpret_cast<float*>(sma + A_STG_B) + wn * (128 * OLD);
    #pragma unroll
    for (int mi = 0; mi < 2; mi++)
        #pragma unroll
        for (int no = 0; no < 8; no++) {
            int row = wm * 32 + mi * 16 + (lane >> 2);
            int col = no * 8 + (lane & 3) * 2;
            *reinterpret_cast<float2*>(&sOb[row * OLD + col]) =
                make_float2(oacc[mi][no][0], oacc[mi][no][1]);
            *reinterpret_cast<float2*>(&sOb[(row + 8) * OLD + col]) =
                make_float2(oacc[mi][no][2], oacc[mi][no][3]);
        }
    __syncthreads();

    float* p0buf = reinterpret_cast<float*>(sma + A_STG_B);
    float* p1buf = p0buf + 128 * OLD;
    #pragma unroll
    for (int i = 0; i < 16; i++) {
        int r = wid * 16 + i;
        float v0 = p0buf[r * OLD + lane]      + p1buf[r * OLD + lane];
        float v1 = p0buf[r * OLD + lane + 32] + p1buf[r * OLD + lane + 32];
        float mx = fmaxf(v0, v1);
        #pragma unroll
        for (int o = 16; o > 0; o >>= 1)
            mx = fmaxf(mx, __shfl_xor_sync(0xffffffffu, mx, o));
        float e0 = __expf(v0 - mx), e1 = __expf(v1 - mx);
        float s = e0 + e1;
        #pragma unroll
        for (int o = 16; o > 0; o >>= 1) s += __shfl_xor_sync(0xffffffffu, s, o);
        float inv = 1.0f / s;
        float q0 = e0 * inv, q1 = e1 * inv;
        size_t g = base + (size_t)(s0 + r) * DK;
        bf16 h0 = __float2bfloat16(q0), h1 = __float2bfloat16(q1);
        Mhi[g + lane]      = h0;
        Mhi[g + lane + 32] = h1;
        Mlo[g + lane]      = __float2bfloat16(q0 - __bfloat162float(h0));
        Mlo[g + lane + 32] = __float2bfloat16(q1 - __bfloat162float(h1));
    }
}

// ===========================================================================
// Launch
// ===========================================================================
extern "C" void kernel_launch(void* const* d_in, const int* in_sizes, int n_in,
                              void* d_out, int out_size)
{
    const float* x  = (const float*)d_in[0];
    const float* Wq = (const float*)d_in[1];
    const float* bq = (const float*)d_in[2];
    const float* Wk = (const float*)d_in[3];
    const float* bk = (const float*)d_in[4];
    const float* Wv = (const float*)d_in[5];
    const float* bv = (const float*)d_in[6];
    const float* Wo = (const float*)d_in[7];
    const float* bo = (const float*)d_in[8];
    const float* Wf = (const float*)d_in[9];
    const float* bf_ = (const float*)d_in[10];
    float* out = (float*)d_out;

    bf16 *xhi, *xlo, *Whi, *Wlo, *WoThi, *WoTlo, *Wchi, *Wclo;
    bf16 *Qhi, *Qlo, *Khi, *Klo, *Vhi, *Vlo, *Mhi, *Mlo;
    float *bp, *zb;
    cudaGetSymbolAddress((void**)&xhi, g_xhi); cudaGetSymbolAddress((void**)&xlo, g_xlo);
    cudaGetSymbolAddress((void**)&Whi, g_Whi); cudaGetSymbolAddress((void**)&Wlo, g_Wlo);
    cudaGetSymbolAddress((void**)&WoThi, g_WoThi); cudaGetSymbolAddress((void**)&WoTlo, g_WoTlo);
    cudaGetSymbolAddress((void**)&Wchi, g_Wchi); cudaGetSymbolAddress((void**)&Wclo, g_Wclo);
    cudaGetSymbolAddress((void**)&Qhi, g_Qhi); cudaGetSymbolAddress((void**)&Qlo, g_Qlo);
    cudaGetSymbolAddress((void**)&Khi, g_Khi); cudaGetSymbolAddress((void**)&Klo, g_Klo);
    cudaGetSymbolAddress((void**)&Vhi, g_Vhi); cudaGetSymbolAddress((void**)&Vlo, g_Vlo);
    cudaGetSymbolAddress((void**)&Mhi, g_Mhi); cudaGetSymbolAddress((void**)&Mlo, g_Mlo);
    cudaGetSymbolAddress((void**)&bp, g_bp); cudaGetSymbolAddress((void**)&zb, g_zb);

    cudaFuncSetAttribute(mma_gemm, cudaFuncAttributeMaxDynamicSharedMemorySize, GEMM_SMEM);
    cudaFuncSetAttribute(qkv_gemm, cudaFuncAttributeMaxDynamicSharedMemorySize, GEMM_SMEM);
    cudaFuncSetAttribute(attn_mma, cudaFuncAttributeMaxDynamicSharedMemorySize, ATTN_SMEM);

    const int WN = DM * DM;

    // converts + Wo transpose + fused bias
    int n4tot = N4X + 4 * N4W;
    cvt_all<<<(n4tot + 255)/256, 256>>>(x, Wq, Wk, Wv, Wf, xhi, xlo, Whi, Wlo);
    dim3 tgrid(DM/32, DM/32);
    trans_wo<<<tgrid, 256>>>(Wo, WoThi, WoTlo);
    bprime_k<<<DM/8, 256>>>(Wf, bo, bf_, bp);

    // Wc = Wf @ Wo, hi/lo output. grid (6, 6)
    dim3 wcgrid(DM/128, DM/128);
    mma_gemm<<<wcgrid, 256, GEMM_SMEM>>>(Whi + 3*(size_t)WN, Wlo + 3*(size_t)WN,
                                         WoThi, WoTlo, zb, nullptr, Wchi, Wclo);

    // QKV projections
    dim3 qgrid(DM/128, MROWS/128, 3);   // (6, 32, 3)
    qkv_gemm<<<qgrid, 256, GEMM_SMEM>>>(xhi, xlo, Whi, Wlo, bq, bk, bv,
                                        Qhi, Qlo, Khi, Klo, Vhi, Vlo);

    // attention (fused softmax -> M hi/lo)
    dim3 agrid(SEQ/128, BD*NH);         // (16, 24)
    attn_mma<<<agrid, 256, ATTN_SMEM>>>(Qhi, Qlo, Khi, Klo, Vhi, Vlo, Mhi, Mlo);

    // single fused output projection: out = M @ Wc^T + b'
    dim3 ggrid(DM/128, MROWS/128);      // (6, 32)
    mma_gemm<<<ggrid, 256, GEMM_SMEM>>>(Mhi, Mlo, Wchi, Wclo, bp, out, nullptr, nullptr);
}

// round 11
// speedup vs baseline: 1.0868x; 1.0868x over previous
#include <cuda_runtime.h>
#include <cuda_bf16.h>

#define BD      2
#define SEQ     2048
#define DM      768
#define NH      12
#define DK      64
#define MROWS   (BD*SEQ)
#define ATT_SCALE 0.125f

typedef __nv_bfloat16 bf16;

// ===========================================================================
// helpers
// ===========================================================================
__device__ __forceinline__ unsigned smem_u32(const void* p) {
    unsigned a;
    asm("{ .reg .u64 t; cvta.to.shared.u64 t, %1; cvt.u32.u64 %0, t; }"
        : "=r"(a) : "l"(p));
    return a;
}
__device__ __forceinline__ void ldsm4(unsigned& r0, unsigned& r1, unsigned& r2,
                                      unsigned& r3, unsigned a) {
    asm volatile("ldmatrix.sync.aligned.m8n8.x4.shared.b16 {%0,%1,%2,%3}, [%4];"
        : "=r"(r0), "=r"(r1), "=r"(r2), "=r"(r3) : "r"(a));
}
__device__ __forceinline__ void ldsm4t(unsigned& r0, unsigned& r1, unsigned& r2,
                                       unsigned& r3, unsigned a) {
    asm volatile("ldmatrix.sync.aligned.m8n8.x4.trans.shared.b16 {%0,%1,%2,%3}, [%4];"
        : "=r"(r0), "=r"(r1), "=r"(r2), "=r"(r3) : "r"(a));
}
__device__ __forceinline__ void mma_bf16(float* c, const unsigned* a,
                                         unsigned b0, unsigned b1) {
    asm volatile("mma.sync.aligned.m16n8k16.row.col.f32.bf16.bf16.f32 "
        "{%0,%1,%2,%3},{%4,%5,%6,%7},{%8,%9},{%0,%1,%2,%3};"
        : "+f"(c[0]), "+f"(c[1]), "+f"(c[2]), "+f"(c[3])
        : "r"(a[0]), "r"(a[1]), "r"(a[2]), "r"(a[3]), "r"(b0), "r"(b1));
}
__device__ __forceinline__ unsigned pack_hilo(float x, float y, unsigned& lo) {
    bf16 hx = __float2bfloat16(x), hy = __float2bfloat16(y);
    bf16 lx = __float2bfloat16(x - __bfloat162float(hx));
    bf16 ly = __float2bfloat16(y - __bfloat162float(hy));
    lo = (unsigned)__bfloat16_as_ushort(lx) | ((unsigned)__bfloat16_as_ushort(ly) << 16);
    return (unsigned)__bfloat16_as_ushort(hx) | ((unsigned)__bfloat16_as_ushort(hy) << 16);
}
#define CPA16(d, s) \
    asm volatile("cp.async.cg.shared.global [%0], [%1], 16;" :: "r"(d), "l"(s) : "memory")
#define CP_COMMIT() asm volatile("cp.async.commit_group;" ::: "memory")
#define CP_WAIT1()  asm volatile("cp.async.wait_group 1;" ::: "memory")
#define CP_WAIT0()  asm volatile("cp.async.wait_group 0;" ::: "memory")

// ===========================================================================
// scratch
// ===========================================================================
__device__ bf16 g_xhi[MROWS*DM], g_xlo[MROWS*DM];
__device__ bf16 g_Whi[4*DM*DM],  g_Wlo[4*DM*DM];     // Wq, Wk, Wv, Wf
__device__ bf16 g_WoThi[DM*DM],  g_WoTlo[DM*DM];
__device__ bf16 g_Wchi[DM*DM],   g_Wclo[DM*DM];      // Wc = Wf @ Wo
__device__ bf16 g_Qhi[MROWS*DM], g_Qlo[MROWS*DM];
__device__ bf16 g_Khi[MROWS*DM], g_Klo[MROWS*DM];
__device__ bf16 g_Vhi[MROWS*DM], g_Vlo[MROWS*DM];
__device__ bf16 g_Mhi[MROWS*DM], g_Mlo[MROWS*DM];
__device__ float g_bp[DM];
__device__ float g_zb[DM];

// ===========================================================================
// merged fp32 -> bf16 hi/lo splitter
// ===========================================================================
#define N4X (MROWS*DM/4)
#define N4W (DM*DM/4)
__global__ void __launch_bounds__(256) cvt_all(
    const float* __restrict__ x,
    const float* __restrict__ Wq, const float* __restrict__ Wk,
    const float* __restrict__ Wv, const float* __restrict__ Wf,
    bf16* __restrict__ xhi, bf16* __restrict__ xlo,
    bf16* __restrict__ Whi, bf16* __restrict__ Wlo)
{
    int i = blockIdx.x * blockDim.x + threadIdx.x;
    const float* src; bf16 *hi, *lo; int off;
    if (i < N4X) { src = x; hi = xhi; lo = xlo; off = i; }
    else {
        int j = i - N4X;
        if (j >= 4 * N4W) return;
        int w = j / N4W;
        off = j - w * N4W;
        src = (w == 0) ? Wq : (w == 1) ? Wk : (w == 2) ? Wv : Wf;
        hi = Whi + (size_t)w * (DM*DM);
        lo = Wlo + (size_t)w * (DM*DM);
    }
    float4 v = reinterpret_cast<const float4*>(src)[off];
    uint2 hp, lp;
    hp.x = pack_hilo(v.x, v.y, lp.x);
    hp.y = pack_hilo(v.z, v.w, lp.y);
    reinterpret_cast<uint2*>(hi)[off] = hp;
    reinterpret_cast<uint2*>(lo)[off] = lp;
}

// ===========================================================================
// Wo transpose + split
// ===========================================================================
__global__ void __launch_bounds__(256) trans_wo(
    const float* __restrict__ Wo, bf16* __restrict__ hi, bf16* __restrict__ lo)
{
    __shared__ float t[32][33];
    int bx = blockIdx.x * 32, by = blockIdx.y * 32;
    int tx = threadIdx.x & 31, ty = threadIdx.x >> 5;
    #pragma unroll
    for (int i = 0; i < 32; i += 8)
        t[ty + i][tx] = Wo[(size_t)(by + ty + i) * DM + bx + tx];
    __syncthreads();
    #pragma unroll
    for (int i = 0; i < 32; i += 8) {
        float v = t[tx][ty + i];
        bf16 h = __float2bfloat16(v);
        bf16 l = __float2bfloat16(v - __bfloat162float(h));
        size_t o = (size_t)(bx + ty + i) * DM + by + tx;
        hi[o] = h;
        lo[o] = l;
    }
}

// ===========================================================================
// b' = Wf @ bo + bf
// ===========================================================================
__global__ void __launch_bounds__(256) bprime_k(
    const float* __restrict__ Wf, const float* __restrict__ bo,
    const float* __restrict__ bfv, float* __restrict__ bp)
{
    int n = blockIdx.x * 8 + (threadIdx.x >> 5);
    int lane = threadIdx.x & 31;
    if (n >= DM) return;
    float s = 0.0f;
    for (int j = lane; j < DM; j += 32) s += Wf[(size_t)n * DM + j] * bo[j];
    #pragma unroll
    for (int o = 16; o > 0; o >>= 1) s += __shfl_xor_sync(0xffffffffu, s, o);
    if (lane == 0) bp[n] = s + bfv[n];
}

// ===========================================================================
// GEMM (round-6 proven config): C = A @ W^T + bias, split-bf16 3-pass,
// cp.async 2-stage. Tile 128x64, K-chunk 64, 8 warps (4M x 2N), warp 32x32.
// ===========================================================================
#define GLD 72
#define G_AH_B 0
#define G_AL_B 18432
#define G_BH_B 36864
#define G_BL_B 46080
#define G_STAGE_B 55296
#define GEMM_SMEM (2*G_STAGE_B)

__device__ __forceinline__ void gemm_core(
    int row0, int col0,
    const bf16* __restrict__ Ahi, const bf16* __restrict__ Alo,
    const bf16* __restrict__ Bhi, const bf16* __restrict__ Blo,
    const float* __restrict__ bias,
    float* __restrict__ Cf, bf16* __restrict__ Chi, bf16* __restrict__ Clo)
{
    extern __shared__ char smc[];
    const int tid = threadIdx.x, lane = tid & 31, wid = tid >> 5;
    const int wm = wid >> 1, wn = wid & 1;
    const unsigned sb = smem_u32(smc);

    float acc[2][4][4];
    #pragma unroll
    for (int i = 0; i < 2; i++)
        #pragma unroll
        for (int j = 0; j < 4; j++)
            #pragma unroll
            for (int k = 0; k < 4; k++) acc[i][j][k] = 0.0f;

    auto issue = [&](int s, int kc) {
        unsigned stg = sb + s * G_STAGE_B;
        #pragma unroll
        for (int u = 0; u < 4; u++) {
            int idx = u * 256 + tid;
            int r = idx >> 3, c = idx & 7;
            const char* ga = (const char*)(Ahi + (size_t)(row0 + r) * DM + kc) + c * 16;
            const char* gl = (const char*)(Alo + (size_t)(row0 + r) * DM + kc) + c * 16;
            unsigned d = (unsigned)(r * GLD + c * 8) * 2;
            CPA16(stg + G_AH_B + d, ga);
            CPA16(stg + G_AL_B + d, gl);
        }
        #pragma unroll
        for (int u = 0; u < 2; u++) {
            int idx = u * 256 + tid;
            int r = idx >> 3, c = idx & 7;
            const char* gh = (const char*)(Bhi + (size_t)(col0 + r) * DM + kc) + c * 16;
            const char* gl = (const char*)(Blo + (size_t)(col0 + r) * DM + kc) + c * 16;
            unsigned d = (unsigned)(r * GLD + c * 8) * 2;
            CPA16(stg + G_BH_B + d, gh);
            CPA16(stg + G_BL_B + d, gl);
        }
    };

    issue(0, 0);
    CP_COMMIT();

    const int NC = DM / 64;   // 12
    for (int c = 0; c < NC; c++) {
        const int p = c & 1;
        CP_WAIT0();
        __syncthreads();
        if (c + 1 < NC) { issue(p ^ 1, (c + 1) * 64); CP_COMMIT(); }

        const unsigned stg = sb + p * G_STAGE_B;
        #pragma unroll
        for (int ks = 0; ks < 4; ks++) {
            const int kr = ks * 16;
            unsigned ah[2][4], al[2][4], bh[2][4], bl[2][4];
            #pragma unroll
            for (int mi = 0; mi < 2; mi++) {
                int m = wm * 32 + mi * 16 + (lane & 15);
                int kk = kr + (lane >> 4) * 8;
                ldsm4(ah[mi][0], ah[mi][1], ah[mi][2], ah[mi][3],
                      stg + G_AH_B + (m * GLD + kk) * 2);
                ldsm4(al[mi][0], al[mi][1], al[mi][2], al[mi][3],
                      stg + G_AL_B + (m * GLD + kk) * 2);
            }
            #pragma unroll
            for (int ni2 = 0; ni2 < 2; ni2++) {
                int n = wn * 32 + ni2 * 16 + (lane >> 4) * 8 + (lane & 7);
                int kk = kr + ((lane >> 3) & 1) * 8;
                ldsm4(bh[ni2][0], bh[ni2][1], bh[ni2][2], bh[ni2][3],
                      stg + G_BH_B + (n * GLD + kk) * 2);
                ldsm4(bl[ni2][0], bl[ni2][1], bl[ni2][2], bl[ni2][3],
                      stg + G_BL_B + (n * GLD + kk) * 2);
            }
            #pragma unroll
            for (int mi = 0; mi < 2; mi++)
                #pragma unroll
                for (int ni = 0; ni < 4; ni++) {
                    unsigned* bhp = &bh[ni >> 1][(ni & 1) * 2];
                    unsigned* blp = &bl[ni >> 1][(ni & 1) * 2];
                    mma_bf16(acc[mi][ni], ah[mi], bhp[0], bhp[1]);
                    mma_bf16(acc[mi][ni], ah[mi], blp[0], blp[1]);
                    mma_bf16(acc[mi][ni], al[mi], bhp[0], bhp[1]);
                }
        }
    }

    #pragma unroll
    for (int mi = 0; mi < 2; mi++)
        #pragma unroll
        for (int ni = 0; ni < 4; ni++) {
            int row = row0 + wm * 32 + mi * 16 + (lane >> 2);
            int col = col0 + wn * 32 + ni * 8 + (lane & 3) * 2;
            float2 bv = *reinterpret_cast<const float2*>(&bias[col]);
            #pragma unroll
            for (int h = 0; h < 2; h++) {
                int r = row + h * 8;
                float vx = acc[mi][ni][h * 2 + 0] + bv.x;
                float vy = acc[mi][ni][h * 2 + 1] + bv.y;
                size_t off = (size_t)r * DM + col;
                if (Cf) *reinterpret_cast<float2*>(&Cf[off]) = make_float2(vx, vy);
                if (Chi) {
                    unsigned lo, hi = pack_hilo(vx, vy, lo);
                    *reinterpret_cast<unsigned*>(&Chi[off]) = hi;
                    *reinterpret_cast<unsigned*>(&Clo[off]) = lo;
                }
            }
        }
}

__global__ void __launch_bounds__(256, 2) mma_gemm(
    const bf16* __restrict__ Ahi, const bf16* __restrict__ Alo,
    const bf16* __restrict__ Bhi, const bf16* __restrict__ Blo,
    const float* __restrict__ bias,
    float* __restrict__ Cf, bf16* __restrict__ Chi, bf16* __restrict__ Clo)
{
    gemm_core(blockIdx.y * 128, blockIdx.x * 64,
              Ahi, Alo, Bhi, Blo, bias, Cf, Chi, Clo);
}

// z = 0,1,2: QKV projections. z = 3 (first 6 y-blocks only): Wc = Wf @ Wo.
__global__ void __launch_bounds__(256, 2) qkv_gemm(
    const bf16* __restrict__ xhi, const bf16* __restrict__ xlo,
    const bf16* __restrict__ Whi, const bf16* __restrict__ Wlo,
    const bf16* __restrict__ WoThi, const bf16* __restrict__ WoTlo,
    const float* __restrict__ bq, const float* __restrict__ bk,
    const float* __restrict__ bv, const float* __restrict__ zb,
    bf16* __restrict__ Qhi, bf16* __restrict__ Qlo,
    bf16* __restrict__ Khi, bf16* __restrict__ Klo,
    bf16* __restrict__ Vhi, bf16* __restrict__ Vlo,
    bf16* __restrict__ Wchi, bf16* __restrict__ Wclo)
{
    const int z = blockIdx.z;
    const int WN = DM * DM;
    if (z == 3) {
        if (blockIdx.y >= DM / 128) return;      // 6 row-tiles for 768
        gemm_core(blockIdx.y * 128, blockIdx.x * 64,
                  Whi + 3*(size_t)WN, Wlo + 3*(size_t)WN, WoThi, WoTlo,
                  zb, nullptr, Wchi, Wclo);
        return;
    }
    const float* bias = (z == 0) ? bq : (z == 1) ? bk : bv;
    bf16* Chi = (z == 0) ? Qhi : (z == 1) ? Khi : Vhi;
    bf16* Clo = (z == 0) ? Qlo : (z == 1) ? Klo : Vlo;
    gemm_core(blockIdx.y * 128, blockIdx.x * 64,
              xhi, xlo, Whi + (size_t)z * WN, Wlo + (size_t)z * WN, bias,
              nullptr, Chi, Clo);
}

// ===========================================================================
// Attention (round-8/9 proven config): 128 Q-rows/block, 8 warps, S register-
// resident, 3-stage cp.async K/V pipeline.
// ===========================================================================
#define ALD 72
#define A_QH_B 0
#define A_QL_B 18432
#define A_STG_B 36864
#define A_STG_SZ 36864
#define A_KH_B 0
#define A_KL_B 9216
#define A_VH_B 18432
#define A_VL_B 27648
#define ATTN_SMEM (36864 + 3*A_STG_SZ)   // 147456
#define OLD 66

__global__ void __launch_bounds__(256) attn_mma(
    const bf16* __restrict__ Qhi, const bf16* __restrict__ Qlo,
    const bf16* __restrict__ Khi, const bf16* __restrict__ Klo,
    const bf16* __restrict__ Vhi, const bf16* __restrict__ Vlo,
    bf16* __restrict__ Mhi, bf16* __restrict__ Mlo)
{
    extern __shared__ char sma[];
    const int tid = threadIdx.x, lane = tid & 31, wid = tid >> 5;
    const int wm = wid >> 1, wn = wid & 1;
    const int bh = blockIdx.y;
    const int s0 = blockIdx.x * 128;
    const size_t base = (size_t)bh * SEQ * DK;
    const unsigned sb = smem_u32(sma);

    #pragma unroll
    for (int u = 0; u < 4; u++) {
        int idx = u * 256 + tid;
        int r = idx >> 3, c = idx & 7;
        size_t g = base + (size_t)(s0 + r) * DK + c * 8;
        *reinterpret_cast<uint4*>(sma + A_QH_B + (r * ALD + c * 8) * 2) =
            *reinterpret_cast<const uint4*>(Qhi + g);
        *reinterpret_cast<uint4*>(sma + A_QL_B + (r * ALD + c * 8) * 2) =
            *reinterpret_cast<const uint4*>(Qlo + g);
    }

    auto issue = [&](int s, int t0) {
        unsigned stg = sb + A_STG_B + s * A_STG_SZ;
        #pragma unroll
        for (int u = 0; u < 2; u++) {
            int idx = u * 256 + tid;
            int r = idx >> 3, c = idx & 7;
            size_t g = (base + (size_t)(t0 + r) * DK) * 2 + c * 16;
            unsigned d = (unsigned)(r * ALD + c * 8) * 2;
            CPA16(stg + A_KH_B + d, (const char*)Khi + g);
            CPA16(stg + A_KL_B + d, (const char*)Klo + g);
            CPA16(stg + A_VH_B + d, (const char*)Vhi + g);
            CPA16(stg + A_VL_B + d, (const char*)Vlo + g);
        }
    };

    float oacc[2][8][4];
    #pragma unroll
    for (int i = 0; i < 2; i++)
        #pragma unroll
        for (int j = 0; j < 8; j++)
            #pragma unroll
            for (int k = 0; k < 4; k++) oacc[i][j][k] = 0.0f;

    issue(0, 0);
    CP_COMMIT();
    issue(1, 64);
    CP_COMMIT();

    const int NC = SEQ / 64;   // 32
    int p = 0;
    for (int c = 0; c < NC; c++) {
        if (c + 1 < NC) { CP_WAIT1(); }
        else            { CP_WAIT0(); }
        __syncthreads();
        if (c + 2 < NC) { issue((p + 2) % 3, (c + 2) * 64); CP_COMMIT(); }

        const unsigned stg = sb + A_STG_B + p * A_STG_SZ;

        float sacc[2][4][4];
        #pragma unroll
        for (int i = 0; i < 2; i++)
            #pragma unroll
            for (int j = 0; j < 4; j++)
                #pragma unroll
                for (int k = 0; k < 4; k++) sacc[i][j][k] = 0.0f;

        #pragma unroll
        for (int ks = 0; ks < 4; ks++) {
            const int kr = ks * 16;
            unsigned ah[2][4], al[2][4], bh_[2][4], bl_[2][4];
            #pragma unroll
            for (int mi = 0; mi < 2; mi++) {
                int m = wm * 32 + mi * 16 + (lane & 15);
                int kk = kr + (lane >> 4) * 8;
                ldsm4(ah[mi][0], ah[mi][1], ah[mi][2], ah[mi][3],
                      sb + A_QH_B + (m * ALD + kk) * 2);
                ldsm4(al[mi][0], al[mi][1], al[mi][2], al[mi][3],
                      sb + A_QL_B + (m * ALD + kk) * 2);
            }
            #pragma unroll
            for (int ni2 = 0; ni2 < 2; ni2++) {
                int n = wn * 32 + ni2 * 16 + (lane >> 4) * 8 + (lane & 7);
                int kk = kr + ((lane >> 3) & 1) * 8;
                ldsm4(bh_[ni2][0], bh_[ni2][1], bh_[ni2][2], bh_[ni2][3],
                      stg + A_KH_B + (n * ALD + kk) * 2);
                ldsm4(bl_[ni2][0], bl_[ni2][1], bl_[ni2][2], bl_[ni2][3],
                      stg + A_KL_B + (n * ALD + kk) * 2);
            }
            #pragma unroll
            for (int mi = 0; mi < 2; mi++)
                #pragma unroll
                for (int ni = 0; ni < 4; ni++) {
                    unsigned* bhp = &bh_[ni >> 1][(ni & 1) * 2];
                    unsigned* blp = &bl_[ni >> 1][(ni & 1) * 2];
                    mma_bf16(sacc[mi][ni], ah[mi], bhp[0], bhp[1]);
                    mma_bf16(sacc[mi][ni], ah[mi], blp[0], blp[1]);
                    mma_bf16(sacc[mi][ni], al[mi], bhp[0], bhp[1]);
                }
        }

        #pragma unroll
        for (int j = 0; j < 2; j++) {
            unsigned sa_h[2][4], sa_l[2][4];
            #pragma unroll
            for (int mi = 0; mi < 2; mi++) {
                float* t0 = sacc[mi][2*j];
                float* t1 = sacc[mi][2*j + 1];
                sa_h[mi][0] = pack_hilo(t0[0]*ATT_SCALE, t0[1]*ATT_SCALE, sa_l[mi][0]);
                sa_h[mi][1] = pack_hilo(t0[2]*ATT_SCALE, t0[3]*ATT_SCALE, sa_l[mi][1]);
                sa_h[mi][2] = pack_hilo(t1[0]*ATT_SCALE, t1[1]*ATT_SCALE, sa_l[mi][2]);
                sa_h[mi][3] = pack_hilo(t1[2]*ATT_SCALE, t1[3]*ATT_SCALE, sa_l[mi][3]);
            }
            int kk = wn * 32 + j * 16 + (lane & 7) + ((lane >> 3) & 1) * 8;
            unsigned vh[4][4], vl[4][4];
            #pragma unroll
            for (int no2 = 0; no2 < 4; no2++) {
                int n = no2 * 16 + (lane >> 4) * 8;
                ldsm4t(vh[no2][0], vh[no2][1], vh[no2][2], vh[no2][3],
                       stg + A_VH_B + (kk * ALD + n) * 2);
                ldsm4t(vl[no2][0], vl[no2][1], vl[no2][2], vl[no2][3],
                       stg + A_VL_B + (kk * ALD + n) * 2);
            }
            #pragma unroll
            for (int mi = 0; mi < 2; mi++)
                #pragma unroll
                for (int no = 0; no < 8; no++) {
                    unsigned* bhp = &vh[no >> 1][(no & 1) * 2];
                    unsigned* blp = &vl[no >> 1][(no & 1) * 2];
                    mma_bf16(oacc[mi][no], sa_h[mi], bhp[0], bhp[1]);
                    mma_bf16(oacc[mi][no], sa_h[mi], blp[0], blp[1]);
                    mma_bf16(oacc[mi][no], sa_l[mi], bhp[0], bhp[1]);
                }
        }
        p = (p + 1) % 3;
    }

    __syncthreads();
    float* sOb = reinterpret_cast<float*>(sma + A_STG_B) + wn * (128 * OLD);
    #pragma unroll
    for (int mi = 0; mi < 2; mi++)
        #pragma unroll
        for (int no = 0; no < 8; no++) {
            int row = wm * 32 + mi * 16 + (lane >> 2);
            int col = no * 8 + (lane & 3) * 2;
            *reinterpret_cast<float2*>(&sOb[row * OLD + col]) =
                make_float2(oacc[mi][no][0], oacc[mi][no][1]);
            *reinterpret_cast<float2*>(&sOb[(row + 8) * OLD + col]) =
                make_float2(oacc[mi][no][2], oacc[mi][no][3]);
        }
    __syncthreads();

    float* p0buf = reinterpret_cast<float*>(sma + A_STG_B);
    float* p1buf = p0buf + 128 * OLD;
    #pragma unroll
    for (int i = 0; i < 16; i++) {
        int r = wid * 16 + i;
        float v0 = p0buf[r * OLD + lane]      + p1buf[r * OLD + lane];
        float v1 = p0buf[r * OLD + lane + 32] + p1buf[r * OLD + lane + 32];
        float mx = fmaxf(v0, v1);
        #pragma unroll
        for (int o = 16; o > 0; o >>= 1)
            mx = fmaxf(mx, __shfl_xor_sync(0xffffffffu, mx, o));
        float e0 = __expf(v0 - mx), e1 = __expf(v1 - mx);
        float s = e0 + e1;
        #pragma unroll
        for (int o = 16; o > 0; o >>= 1) s += __shfl_xor_sync(0xffffffffu, s, o);
        float inv = 1.0f / s;
        float q0 = e0 * inv, q1 = e1 * inv;
        size_t g = base + (size_t)(s0 + r) * DK;
        bf16 h0 = __float2bfloat16(q0), h1 = __float2bfloat16(q1);
        Mhi[g + lane]      = h0;
        Mhi[g + lane + 32] = h1;
        Mlo[g + lane]      = __float2bfloat16(q0 - __bfloat162float(h0));
        Mlo[g + lane + 32] = __float2bfloat16(q1 - __bfloat162float(h1));
    }
}

// ===========================================================================
// Launch
// ===========================================================================
extern "C" void kernel_launch(void* const* d_in, const int* in_sizes, int n_in,
                              void* d_out, int out_size)
{
    const float* x  = (const float*)d_in[0];
    const float* Wq = (const float*)d_in[1];
    const float* bq = (const float*)d_in[2];
    const float* Wk = (const float*)d_in[3];
    const float* bk = (const float*)d_in[4];
    const float* Wv = (const float*)d_in[5];
    const float* bv = (const float*)d_in[6];
    const float* Wo = (const float*)d_in[7];
    const float* bo = (const float*)d_in[8];
    const float* Wf = (const float*)d_in[9];
    const float* bf_ = (const float*)d_in[10];
    float* out = (float*)d_out;

    bf16 *xhi, *xlo, *Whi, *Wlo, *WoThi, *WoTlo, *Wchi, *Wclo;
    bf16 *Qhi, *Qlo, *Khi, *Klo, *Vhi, *Vlo, *Mhi, *Mlo;
    float *bp, *zb;
    cudaGetSymbolAddress((void**)&xhi, g_xhi); cudaGetSymbolAddress((void**)&xlo, g_xlo);
    cudaGetSymbolAddress((void**)&Whi, g_Whi); cudaGetSymbolAddress((void**)&Wlo, g_Wlo);
    cudaGetSymbolAddress((void**)&WoThi, g_WoThi); cudaGetSymbolAddress((void**)&WoTlo, g_WoTlo);
    cudaGetSymbolAddress((void**)&Wchi, g_Wchi); cudaGetSymbolAddress((void**)&Wclo, g_Wclo);
    cudaGetSymbolAddress((void**)&Qhi, g_Qhi); cudaGetSymbolAddress((void**)&Qlo, g_Qlo);
    cudaGetSymbolAddress((void**)&Khi, g_Khi); cudaGetSymbolAddress((void**)&Klo, g_Klo);
    cudaGetSymbolAddress((void**)&Vhi, g_Vhi); cudaGetSymbolAddress((void**)&Vlo, g_Vlo);
    cudaGetSymbolAddress((void**)&Mhi, g_Mhi); cudaGetSymbolAddress((void**)&Mlo, g_Mlo);
    cudaGetSymbolAddress((void**)&bp, g_bp); cudaGetSymbolAddress((void**)&zb, g_zb);

    cudaFuncSetAttribute(mma_gemm, cudaFuncAttributeMaxDynamicSharedMemorySize, GEMM_SMEM);
    cudaFuncSetAttribute(qkv_gemm, cudaFuncAttributeMaxDynamicSharedMemorySize, GEMM_SMEM);
    cudaFuncSetAttribute(attn_mma, cudaFuncAttributeMaxDynamicSharedMemorySize, ATTN_SMEM);

    // converts + Wo transpose + fused bias
    int n4tot = N4X + 4 * N4W;
    cvt_all<<<(n4tot + 255)/256, 256>>>(x, Wq, Wk, Wv, Wf, xhi, xlo, Whi, Wlo);
    dim3 tgrid(DM/32, DM/32);
    trans_wo<<<tgrid, 256>>>(Wo, WoThi, WoTlo);
    bprime_k<<<DM/8, 256>>>(Wf, bo, bf_, bp);

    // QKV projections + Wc = Wf@Wo folded in as z=3 (y<6 active)
    dim3 qgrid(DM/64, MROWS/128, 4);   // (12, 32, 4)
    qkv_gemm<<<qgrid, 256, GEMM_SMEM>>>(xhi, xlo, Whi, Wlo, WoThi, WoTlo,
                                        bq, bk, bv, zb,
                                        Qhi, Qlo, Khi, Klo, Vhi, Vlo,
                                        Wchi, Wclo);

    // attention (fused softmax -> M hi/lo)
    dim3 agrid(SEQ/128, BD*NH);        // (16, 24)
    attn_mma<<<agrid, 256, ATTN_SMEM>>>(Qhi, Qlo, Khi, Klo, Vhi, Vlo, Mhi, Mlo);

    // single fused output projection: out = M @ Wc^T + b'
    dim3 ggrid(DM/64, MROWS/128);      // (12, 32)
    mma_gemm<<<ggrid, 256, GEMM_SMEM>>>(Mhi, Mlo, Wchi, Wclo, bp, out, nullptr, nullptr);
}

// round 12
// speedup vs baseline: 1.0997x; 1.0119x over previous
#include <cuda_runtime.h>
#include <cuda_bf16.h>

#define BD      2
#define SEQ     2048
#define DM      768
#define NH      12
#define DK      64
#define MROWS   (BD*SEQ)
#define ATT_SCALE 0.125f

typedef __nv_bfloat16 bf16;

// ===========================================================================
// helpers
// ===========================================================================
__device__ __forceinline__ unsigned smem_u32(const void* p) {
    unsigned a;
    asm("{ .reg .u64 t; cvta.to.shared.u64 t, %1; cvt.u32.u64 %0, t; }"
        : "=r"(a) : "l"(p));
    return a;
}
__device__ __forceinline__ void ldsm4(unsigned& r0, unsigned& r1, unsigned& r2,
                                      unsigned& r3, unsigned a) {
    asm volatile("ldmatrix.sync.aligned.m8n8.x4.shared.b16 {%0,%1,%2,%3}, [%4];"
        : "=r"(r0), "=r"(r1), "=r"(r2), "=r"(r3) : "r"(a));
}
__device__ __forceinline__ void ldsm4t(unsigned& r0, unsigned& r1, unsigned& r2,
                                       unsigned& r3, unsigned a) {
    asm volatile("ldmatrix.sync.aligned.m8n8.x4.trans.shared.b16 {%0,%1,%2,%3}, [%4];"
        : "=r"(r0), "=r"(r1), "=r"(r2), "=r"(r3) : "r"(a));
}
__device__ __forceinline__ void mma_bf16(float* c, const unsigned* a,
                                         unsigned b0, unsigned b1) {
    asm volatile("mma.sync.aligned.m16n8k16.row.col.f32.bf16.bf16.f32 "
        "{%0,%1,%2,%3},{%4,%5,%6,%7},{%8,%9},{%0,%1,%2,%3};"
        : "+f"(c[0]), "+f"(c[1]), "+f"(c[2]), "+f"(c[3])
        : "r"(a[0]), "r"(a[1]), "r"(a[2]), "r"(a[3]), "r"(b0), "r"(b1));
}
__device__ __forceinline__ unsigned pack_hilo(float x, float y, unsigned& lo) {
    bf16 hx = __float2bfloat16(x), hy = __float2bfloat16(y);
    bf16 lx = __float2bfloat16(x - __bfloat162float(hx));
    bf16 ly = __float2bfloat16(y - __bfloat162float(hy));
    lo = (unsigned)__bfloat16_as_ushort(lx) | ((unsigned)__bfloat16_as_ushort(ly) << 16);
    return (unsigned)__bfloat16_as_ushort(hx) | ((unsigned)__bfloat16_as_ushort(hy) << 16);
}
#define CPA16(d, s) \
    asm volatile("cp.async.cg.shared.global [%0], [%1], 16;" :: "r"(d), "l"(s) : "memory")
#define CP_COMMIT() asm volatile("cp.async.commit_group;" ::: "memory")
#define CP_WAIT1()  asm volatile("cp.async.wait_group 1;" ::: "memory")
#define CP_WAIT0()  asm volatile("cp.async.wait_group 0;" ::: "memory")

// ===========================================================================
// scratch
// ===========================================================================
__device__ bf16 g_xhi[MROWS*DM], g_xlo[MROWS*DM];
__device__ bf16 g_Whi[4*DM*DM],  g_Wlo[4*DM*DM];     // Wq, Wk, Wv, Wf
__device__ bf16 g_WoThi[DM*DM],  g_WoTlo[DM*DM];
__device__ bf16 g_Wchi[DM*DM],   g_Wclo[DM*DM];      // Wc = Wf @ Wo
__device__ bf16 g_Qhi[MROWS*DM], g_Qlo[MROWS*DM];
__device__ bf16 g_Khi[MROWS*DM], g_Klo[MROWS*DM];
__device__ bf16 g_Vhi[MROWS*DM], g_Vlo[MROWS*DM];
__device__ bf16 g_Mhi[MROWS*DM], g_Mlo[MROWS*DM];
__device__ float g_bp[DM];
__device__ float g_zb[DM];

// ===========================================================================
// merged fp32 -> bf16 hi/lo splitter
// ===========================================================================
#define N4X (MROWS*DM/4)
#define N4W (DM*DM/4)
__global__ void __launch_bounds__(256) cvt_all(
    const float* __restrict__ x,
    const float* __restrict__ Wq, const float* __restrict__ Wk,
    const float* __restrict__ Wv, const float* __restrict__ Wf,
    bf16* __restrict__ xhi, bf16* __restrict__ xlo,
    bf16* __restrict__ Whi, bf16* __restrict__ Wlo)
{
    int i = blockIdx.x * blockDim.x + threadIdx.x;
    const float* src; bf16 *hi, *lo; int off;
    if (i < N4X) { src = x; hi = xhi; lo = xlo; off = i; }
    else {
        int j = i - N4X;
        if (j >= 4 * N4W) return;
        int w = j / N4W;
        off = j - w * N4W;
        src = (w == 0) ? Wq : (w == 1) ? Wk : (w == 2) ? Wv : Wf;
        hi = Whi + (size_t)w * (DM*DM);
        lo = Wlo + (size_t)w * (DM*DM);
    }
    float4 v = reinterpret_cast<const float4*>(src)[off];
    uint2 hp, lp;
    hp.x = pack_hilo(v.x, v.y, lp.x);
    hp.y = pack_hilo(v.z, v.w, lp.y);
    reinterpret_cast<uint2*>(hi)[off] = hp;
    reinterpret_cast<uint2*>(lo)[off] = lp;
}

// ===========================================================================
// Wo transpose + split
// ===========================================================================
__global__ void __launch_bounds__(256) trans_wo(
    const float* __restrict__ Wo, bf16* __restrict__ hi, bf16* __restrict__ lo)
{
    __shared__ float t[32][33];
    int bx = blockIdx.x * 32, by = blockIdx.y * 32;
    int tx = threadIdx.x & 31, ty = threadIdx.x >> 5;
    #pragma unroll
    for (int i = 0; i < 32; i += 8)
        t[ty + i][tx] = Wo[(size_t)(by + ty + i) * DM + bx + tx];
    __syncthreads();
    #pragma unroll
    for (int i = 0; i < 32; i += 8) {
        float v = t[tx][ty + i];
        bf16 h = __float2bfloat16(v);
        bf16 l = __float2bfloat16(v - __bfloat162float(h));
        size_t o = (size_t)(bx + ty + i) * DM + by + tx;
        hi[o] = h;
        lo[o] = l;
    }
}

// ===========================================================================
// b' = Wf @ bo + bf
// ===========================================================================
__global__ void __launch_bounds__(256) bprime_k(
    const float* __restrict__ Wf, const float* __restrict__ bo,
    const float* __restrict__ bfv, float* __restrict__ bp)
{
    int n = blockIdx.x * 8 + (threadIdx.x >> 5);
    int lane = threadIdx.x & 31;
    if (n >= DM) return;
    float s = 0.0f;
    for (int j = lane; j < DM; j += 32) s += Wf[(size_t)n * DM + j] * bo[j];
    #pragma unroll
    for (int o = 16; o > 0; o >>= 1) s += __shfl_xor_sync(0xffffffffu, s, o);
    if (lane == 0) bp[n] = s + bfv[n];
}

// ===========================================================================
// GEMM (round-6 proven config): C = A @ W^T + bias, split-bf16 3-pass,
// cp.async 2-stage. Tile 128x64, K-chunk 64, 8 warps (4M x 2N), warp 32x32.
// ===========================================================================
#define GLD 72
#define G_AH_B 0
#define G_AL_B 18432
#define G_BH_B 36864
#define G_BL_B 46080
#define G_STAGE_B 55296
#define GEMM_SMEM (2*G_STAGE_B)

__device__ __forceinline__ void gemm_core(
    int row0, int col0,
    const bf16* __restrict__ Ahi, const bf16* __restrict__ Alo,
    const bf16* __restrict__ Bhi, const bf16* __restrict__ Blo,
    const float* __restrict__ bias,
    float* __restrict__ Cf, bf16* __restrict__ Chi, bf16* __restrict__ Clo)
{
    extern __shared__ char smc[];
    const int tid = threadIdx.x, lane = tid & 31, wid = tid >> 5;
    const int wm = wid >> 1, wn = wid & 1;
    const unsigned sb = smem_u32(smc);

    float acc[2][4][4];
    #pragma unroll
    for (int i = 0; i < 2; i++)
        #pragma unroll
        for (int j = 0; j < 4; j++)
            #pragma unroll
            for (int k = 0; k < 4; k++) acc[i][j][k] = 0.0f;

    auto issue = [&](int s, int kc) {
        unsigned stg = sb + s * G_STAGE_B;
        #pragma unroll
        for (int u = 0; u < 4; u++) {
            int idx = u * 256 + tid;
            int r = idx >> 3, c = idx & 7;
            const char* ga = (const char*)(Ahi + (size_t)(row0 + r) * DM + kc) + c * 16;
            const char* gl = (const char*)(Alo + (size_t)(row0 + r) * DM + kc) + c * 16;
            unsigned d = (unsigned)(r * GLD + c * 8) * 2;
            CPA16(stg + G_AH_B + d, ga);
            CPA16(stg + G_AL_B + d, gl);
        }
        #pragma unroll
        for (int u = 0; u < 2; u++) {
            int idx = u * 256 + tid;
            int r = idx >> 3, c = idx & 7;
            const char* gh = (const char*)(Bhi + (size_t)(col0 + r) * DM + kc) + c * 16;
            const char* gl = (const char*)(Blo + (size_t)(col0 + r) * DM + kc) + c * 16;
            unsigned d = (unsigned)(r * GLD + c * 8) * 2;
            CPA16(stg + G_BH_B + d, gh);
            CPA16(stg + G_BL_B + d, gl);
        }
    };

    issue(0, 0);
    CP_COMMIT();

    const int NC = DM / 64;   // 12
    for (int c = 0; c < NC; c++) {
        const int p = c & 1;
        CP_WAIT0();
        __syncthreads();
        if (c + 1 < NC) { issue(p ^ 1, (c + 1) * 64); CP_COMMIT(); }

        const unsigned stg = sb + p * G_STAGE_B;
        #pragma unroll
        for (int ks = 0; ks < 4; ks++) {
            const int kr = ks * 16;
            unsigned ah[2][4], al[2][4], bh[2][4], bl[2][4];
            #pragma unroll
            for (int mi = 0; mi < 2; mi++) {
                int m = wm * 32 + mi * 16 + (lane & 15);
                int kk = kr + (lane >> 4) * 8;
                ldsm4(ah[mi][0], ah[mi][1], ah[mi][2], ah[mi][3],
                      stg + G_AH_B + (m * GLD + kk) * 2);
                ldsm4(al[mi][0], al[mi][1], al[mi][2], al[mi][3],
                      stg + G_AL_B + (m * GLD + kk) * 2);
            }
            #pragma unroll
            for (int ni2 = 0; ni2 < 2; ni2++) {
                int n = wn * 32 + ni2 * 16 + (lane >> 4) * 8 + (lane & 7);
                int kk = kr + ((lane >> 3) & 1) * 8;
                ldsm4(bh[ni2][0], bh[ni2][1], bh[ni2][2], bh[ni2][3],
                      stg + G_BH_B + (n * GLD + kk) * 2);
                ldsm4(bl[ni2][0], bl[ni2][1], bl[ni2][2], bl[ni2][3],
                      stg + G_BL_B + (n * GLD + kk) * 2);
            }
            #pragma unroll
            for (int mi = 0; mi < 2; mi++)
                #pragma unroll
                for (int ni = 0; ni < 4; ni++) {
                    unsigned* bhp = &bh[ni >> 1][(ni & 1) * 2];
                    unsigned* blp = &bl[ni >> 1][(ni & 1) * 2];
                    mma_bf16(acc[mi][ni], ah[mi], bhp[0], bhp[1]);
                    mma_bf16(acc[mi][ni], ah[mi], blp[0], blp[1]);
                    mma_bf16(acc[mi][ni], al[mi], bhp[0], bhp[1]);
                }
        }
    }

    #pragma unroll
    for (int mi = 0; mi < 2; mi++)
        #pragma unroll
        for (int ni = 0; ni < 4; ni++) {
            int row = row0 + wm * 32 + mi * 16 + (lane >> 2);
            int col = col0 + wn * 32 + ni * 8 + (lane & 3) * 2;
            float2 bv = *reinterpret_cast<const float2*>(&bias[col]);
            #pragma unroll
            for (int h = 0; h < 2; h++) {
                int r = row + h * 8;
                float vx = acc[mi][ni][h * 2 + 0] + bv.x;
                float vy = acc[mi][ni][h * 2 + 1] + bv.y;
                size_t off = (size_t)r * DM + col;
                if (Cf) *reinterpret_cast<float2*>(&Cf[off]) = make_float2(vx, vy);
                if (Chi) {
                    unsigned lo, hi = pack_hilo(vx, vy, lo);
                    *reinterpret_cast<unsigned*>(&Chi[off]) = hi;
                    *reinterpret_cast<unsigned*>(&Clo[off]) = lo;
                }
            }
        }
}

__global__ void __launch_bounds__(256, 2) mma_gemm(
    const bf16* __restrict__ Ahi, const bf16* __restrict__ Alo,
    const bf16* __restrict__ Bhi, const bf16* __restrict__ Blo,
    const float* __restrict__ bias,
    float* __restrict__ Cf, bf16* __restrict__ Chi, bf16* __restrict__ Clo)
{
    gemm_core(blockIdx.y * 128, blockIdx.x * 64,
              Ahi, Alo, Bhi, Blo, bias, Cf, Chi, Clo);
}

// z = 0,1,2: QKV projections. z = 3 (first 6 y-blocks only): Wc = Wf @ Wo.
__global__ void __launch_bounds__(256, 2) qkv_gemm(
    const bf16* __restrict__ xhi, const bf16* __restrict__ xlo,
    const bf16* __restrict__ Whi, const bf16* __restrict__ Wlo,
    const bf16* __restrict__ WoThi, const bf16* __restrict__ WoTlo,
    const float* __restrict__ bq, const float* __restrict__ bk,
    const float* __restrict__ bv, const float* __restrict__ zb,
    bf16* __restrict__ Qhi, bf16* __restrict__ Qlo,
    bf16* __restrict__ Khi, bf16* __restrict__ Klo,
    bf16* __restrict__ Vhi, bf16* __restrict__ Vlo,
    bf16* __restrict__ Wchi, bf16* __restrict__ Wclo)
{
    const int z = blockIdx.z;
    const int WN = DM * DM;
    if (z == 3) {
        if (blockIdx.y >= DM / 128) return;
        gemm_core(blockIdx.y * 128, blockIdx.x * 64,
                  Whi + 3*(size_t)WN, Wlo + 3*(size_t)WN, WoThi, WoTlo,
                  zb, nullptr, Wchi, Wclo);
        return;
    }
    const float* bias = (z == 0) ? bq : (z == 1) ? bk : bv;
    bf16* Chi = (z == 0) ? Qhi : (z == 1) ? Khi : Vhi;
    bf16* Clo = (z == 0) ? Qlo : (z == 1) ? Klo : Vlo;
    gemm_core(blockIdx.y * 128, blockIdx.x * 64,
              xhi, xlo, Whi + (size_t)z * WN, Wlo + (size_t)z * WN, bias,
              nullptr, Chi, Clo);
}

// ===========================================================================
// Attention: 128 Q-rows/block, 8 warps, S register-resident, 3-stage cp.async
// K/V pipeline. Q FRAGMENTS HOISTED INTO REGISTERS (loop-invariant).
// ===========================================================================
#define ALD 72
#define A_QH_B 0
#define A_QL_B 18432
#define A_STG_B 36864
#define A_STG_SZ 36864
#define A_KH_B 0
#define A_KL_B 9216
#define A_VH_B 18432
#define A_VL_B 27648
#define ATTN_SMEM (36864 + 3*A_STG_SZ)   // 147456
#define OLD 66

__global__ void __launch_bounds__(256) attn_mma(
    const bf16* __restrict__ Qhi, const bf16* __restrict__ Qlo,
    const bf16* __restrict__ Khi, const bf16* __restrict__ Klo,
    const bf16* __restrict__ Vhi, const bf16* __restrict__ Vlo,
    bf16* __restrict__ Mhi, bf16* __restrict__ Mlo)
{
    extern __shared__ char sma[];
    const int tid = threadIdx.x, lane = tid & 31, wid = tid >> 5;
    const int wm = wid >> 1, wn = wid & 1;
    const int bh = blockIdx.y;
    const int s0 = blockIdx.x * 128;
    const size_t base = (size_t)bh * SEQ * DK;
    const unsigned sb = smem_u32(sma);

    // fill Q smem (128x64 hi/lo)
    #pragma unroll
    for (int u = 0; u < 4; u++) {
        int idx = u * 256 + tid;
        int r = idx >> 3, c = idx & 7;
        size_t g = base + (size_t)(s0 + r) * DK + c * 8;
        *reinterpret_cast<uint4*>(sma + A_QH_B + (r * ALD + c * 8) * 2) =
            *reinterpret_cast<const uint4*>(Qhi + g);
        *reinterpret_cast<uint4*>(sma + A_QL_B + (r * ALD + c * 8) * 2) =
            *reinterpret_cast<const uint4*>(Qlo + g);
    }

    auto issue = [&](int s, int t0) {
        unsigned stg = sb + A_STG_B + s * A_STG_SZ;
        #pragma unroll
        for (int u = 0; u < 2; u++) {
            int idx = u * 256 + tid;
            int r = idx >> 3, c = idx & 7;
            size_t g = (base + (size_t)(t0 + r) * DK) * 2 + c * 16;
            unsigned d = (unsigned)(r * ALD + c * 8) * 2;
            CPA16(stg + A_KH_B + d, (const char*)Khi + g);
            CPA16(stg + A_KL_B + d, (const char*)Klo + g);
            CPA16(stg + A_VH_B + d, (const char*)Vhi + g);
            CPA16(stg + A_VL_B + d, (const char*)Vlo + g);
        }
    };

    issue(0, 0);
    CP_COMMIT();
    issue(1, 64);
    CP_COMMIT();

    // hoist Q fragments into registers (loop-invariant across t-chunks)
    __syncthreads();
    unsigned qh[4][2][4], ql[4][2][4];      // [ks][mi][reg]
    #pragma unroll
    for (int ks = 0; ks < 4; ks++)
        #pragma unroll
        for (int mi = 0; mi < 2; mi++) {
            int m = wm * 32 + mi * 16 + (lane & 15);
            int kk = ks * 16 + (lane >> 4) * 8;
            ldsm4(qh[ks][mi][0], qh[ks][mi][1], qh[ks][mi][2], qh[ks][mi][3],
                  sb + A_QH_B + (m * ALD + kk) * 2);
            ldsm4(ql[ks][mi][0], ql[ks][mi][1], ql[ks][mi][2], ql[ks][mi][3],
                  sb + A_QL_B + (m * ALD + kk) * 2);
        }

    float oacc[2][8][4];
    #pragma unroll
    for (int i = 0; i < 2; i++)
        #pragma unroll
        for (int j = 0; j < 8; j++)
            #pragma unroll
            for (int k = 0; k < 4; k++) oacc[i][j][k] = 0.0f;

    const int NC = SEQ / 64;   // 32
    int p = 0;
    for (int c = 0; c < NC; c++) {
        if (c + 1 < NC) { CP_WAIT1(); }
        else            { CP_WAIT0(); }
        __syncthreads();
        if (c + 2 < NC) { issue((p + 2) % 3, (c + 2) * 64); CP_COMMIT(); }

        const unsigned stg = sb + A_STG_B + p * A_STG_SZ;

        float sacc[2][4][4];
        #pragma unroll
        for (int i = 0; i < 2; i++)
            #pragma unroll
            for (int j = 0; j < 4; j++)
                #pragma unroll
                for (int k = 0; k < 4; k++) sacc[i][j][k] = 0.0f;

        #pragma unroll
        for (int ks = 0; ks < 4; ks++) {
            const int kr = ks * 16;
            unsigned bh_[2][4], bl_[2][4];
            #pragma unroll
            for (int ni2 = 0; ni2 < 2; ni2++) {
                int n = wn * 32 + ni2 * 16 + (lane >> 4) * 8 + (lane & 7);
                int kk = kr + ((lane >> 3) & 1) * 8;
                ldsm4(bh_[ni2][0], bh_[ni2][1], bh_[ni2][2], bh_[ni2][3],
                      stg + A_KH_B + (n * ALD + kk) * 2);
                ldsm4(bl_[ni2][0], bl_[ni2][1], bl_[ni2][2], bl_[ni2][3],
                      stg + A_KL_B + (n * ALD + kk) * 2);
            }
            #pragma unroll
            for (int mi = 0; mi < 2; mi++)
                #pragma unroll
                for (int ni = 0; ni < 4; ni++) {
                    unsigned* bhp = &bh_[ni >> 1][(ni & 1) * 2];
                    unsigned* blp = &bl_[ni >> 1][(ni & 1) * 2];
                    mma_bf16(sacc[mi][ni], qh[ks][mi], bhp[0], bhp[1]);
                    mma_bf16(sacc[mi][ni], qh[ks][mi], blp[0], blp[1]);
                    mma_bf16(sacc[mi][ni], ql[ks][mi], bhp[0], bhp[1]);
                }
        }

        #pragma unroll
        for (int j = 0; j < 2; j++) {
            unsigned sa_h[2][4], sa_l[2][4];
            #pragma unroll
            for (int mi = 0; mi < 2; mi++) {
                float* t0 = sacc[mi][2*j];
                float* t1 = sacc[mi][2*j + 1];
                sa_h[mi][0] = pack_hilo(t0[0]*ATT_SCALE, t0[1]*ATT_SCALE, sa_l[mi][0]);
                sa_h[mi][1] = pack_hilo(t0[2]*ATT_SCALE, t0[3]*ATT_SCALE, sa_l[mi][1]);
                sa_h[mi][2] = pack_hilo(t1[0]*ATT_SCALE, t1[1]*ATT_SCALE, sa_l[mi][2]);
                sa_h[mi][3] = pack_hilo(t1[2]*ATT_SCALE, t1[3]*ATT_SCALE, sa_l[mi][3]);
            }
            int kk = wn * 32 + j * 16 + (lane & 7) + ((lane >> 3) & 1) * 8;
            unsigned vh[4][4], vl[4][4];
            #pragma unroll
            for (int no2 = 0; no2 < 4; no2++) {
                int n = no2 * 16 + (lane >> 4) * 8;
                ldsm4t(vh[no2][0], vh[no2][1], vh[no2][2], vh[no2][3],
                       stg + A_VH_B + (kk * ALD + n) * 2);
                ldsm4t(vl[no2][0], vl[no2][1], vl[no2][2], vl[no2][3],
                       stg + A_VL_B + (kk * ALD + n) * 2);
            }
            #pragma unroll
            for (int mi = 0; mi < 2; mi++)
                #pragma unroll
                for (int no = 0; no < 8; no++) {
                    unsigned* bhp = &vh[no >> 1][(no & 1) * 2];
                    unsigned* blp = &vl[no >> 1][(no & 1) * 2];
                    mma_bf16(oacc[mi][no], sa_h[mi], bhp[0], bhp[1]);
                    mma_bf16(oacc[mi][no], sa_h[mi], blp[0], blp[1]);
                    mma_bf16(oacc[mi][no], sa_l[mi], bhp[0], bhp[1]);
                }
        }
        p = (p + 1) % 3;
    }

    __syncthreads();
    float* sOb = reinterpret_cast<float*>(sma + A_STG_B) + wn * (128 * OLD);
    #pragma unroll
    for (int mi = 0; mi < 2; mi++)
        #pragma unroll
        for (int no = 0; no < 8; no++) {
            int row = wm * 32 + mi * 16 + (lane >> 2);
            int col = no * 8 + (lane & 3) * 2;
            *reinterpret_cast<float2*>(&sOb[row * OLD + col]) =
                make_float2(oacc[mi][no][0], oacc[mi][no][1]);
            *reinterpret_cast<float2*>(&sOb[(row + 8) * OLD + col]) =
                make_float2(oacc[mi][no][2], oacc[mi][no][3]);
        }
    __syncthreads();

    float* p0buf = reinterpret_cast<float*>(sma + A_STG_B);
    float* p1buf = p0buf + 128 * OLD;
    #pragma unroll
    for (int i = 0; i < 16; i++) {
        int r = wid * 16 + i;
        float v0 = p0buf[r * OLD + lane]      + p1buf[r * OLD + lane];
        float v1 = p0buf[r * OLD + lane + 32] + p1buf[r * OLD + lane + 32];
        float mx = fmaxf(v0, v1);
        #pragma unroll
        for (int o = 16; o > 0; o >>= 1)
            mx = fmaxf(mx, __shfl_xor_sync(0xffffffffu, mx, o));
        float e0 = __expf(v0 - mx), e1 = __expf(v1 - mx);
        float s = e0 + e1;
        #pragma unroll
        for (int o = 16; o > 0; o >>= 1) s += __shfl_xor_sync(0xffffffffu, s, o);
        float inv = 1.0f / s;
        float q0 = e0 * inv, q1 = e1 * inv;
        size_t g = base + (size_t)(s0 + r) * DK;
        bf16 h0 = __float2bfloat16(q0), h1 = __float2bfloat16(q1);
        Mhi[g + lane]      = h0;
        Mhi[g + lane + 32] = h1;
        Mlo[g + lane]      = __float2bfloat16(q0 - __bfloat162float(h0));
        Mlo[g + lane + 32] = __float2bfloat16(q1 - __bfloat162float(h1));
    }
}

// ===========================================================================
// Launch
// ===========================================================================
extern "C" void kernel_launch(void* const* d_in, const int* in_sizes, int n_in,
                              void* d_out, int out_size)
{
    const float* x  = (const float*)d_in[0];
    const float* Wq = (const float*)d_in[1];
    const float* bq = (const float*)d_in[2];
    const float* Wk = (const float*)d_in[3];
    const float* bk = (const float*)d_in[4];
    const float* Wv = (const float*)d_in[5];
    const float* bv = (const float*)d_in[6];
    const float* Wo = (const float*)d_in[7];
    const float* bo = (const float*)d_in[8];
    const float* Wf = (const float*)d_in[9];
    const float* bf_ = (const float*)d_in[10];
    float* out = (float*)d_out;

    bf16 *xhi, *xlo, *Whi, *Wlo, *WoThi, *WoTlo, *Wchi, *Wclo;
    bf16 *Qhi, *Qlo, *Khi, *Klo, *Vhi, *Vlo, *Mhi, *Mlo;
    float *bp, *zb;
    cudaGetSymbolAddress((void**)&xhi, g_xhi); cudaGetSymbolAddress((void**)&xlo, g_xlo);
    cudaGetSymbolAddress((void**)&Whi, g_Whi); cudaGetSymbolAddress((void**)&Wlo, g_Wlo);
    cudaGetSymbolAddress((void**)&WoThi, g_WoThi); cudaGetSymbolAddress((void**)&WoTlo, g_WoTlo);
    cudaGetSymbolAddress((void**)&Wchi, g_Wchi); cudaGetSymbolAddress((void**)&Wclo, g_Wclo);
    cudaGetSymbolAddress((void**)&Qhi, g_Qhi); cudaGetSymbolAddress((void**)&Qlo, g_Qlo);
    cudaGetSymbolAddress((void**)&Khi, g_Khi); cudaGetSymbolAddress((void**)&Klo, g_Klo);
    cudaGetSymbolAddress((void**)&Vhi, g_Vhi); cudaGetSymbolAddress((void**)&Vlo, g_Vlo);
    cudaGetSymbolAddress((void**)&Mhi, g_Mhi); cudaGetSymbolAddress((void**)&Mlo, g_Mlo);
    cudaGetSymbolAddress((void**)&bp, g_bp); cudaGetSymbolAddress((void**)&zb, g_zb);

    cudaFuncSetAttribute(mma_gemm, cudaFuncAttributeMaxDynamicSharedMemorySize, GEMM_SMEM);
    cudaFuncSetAttribute(qkv_gemm, cudaFuncAttributeMaxDynamicSharedMemorySize, GEMM_SMEM);
    cudaFuncSetAttribute(attn_mma, cudaFuncAttributeMaxDynamicSharedMemorySize, ATTN_SMEM);

    // converts + Wo transpose + fused bias
    int n4tot = N4X + 4 * N4W;
    cvt_all<<<(n4tot + 255)/256, 256>>>(x, Wq, Wk, Wv, Wf, xhi, xlo, Whi, Wlo);
    dim3 tgrid(DM/32, DM/32);
    trans_wo<<<tgrid, 256>>>(Wo, WoThi, WoTlo);
    bprime_k<<<DM/8, 256>>>(Wf, bo, bf_, bp);

    // QKV projections + Wc = Wf@Wo folded in as z=3 (y<6 active)
    dim3 qgrid(DM/64, MROWS/128, 4);   // (12, 32, 4)
    qkv_gemm<<<qgrid, 256, GEMM_SMEM>>>(xhi, xlo, Whi, Wlo, WoThi, WoTlo,
                                        bq, bk, bv, zb,
                                        Qhi, Qlo, Khi, Klo, Vhi, Vlo,
                                        Wchi, Wclo);

    // attention (fused softmax -> M hi/lo)
    dim3 agrid(SEQ/128, BD*NH);        // (16, 24)
    attn_mma<<<agrid, 256, ATTN_SMEM>>>(Qhi, Qlo, Khi, Klo, Vhi, Vlo, Mhi, Mlo);

    // single fused output projection: out = M @ Wc^T + b'
    dim3 ggrid(DM/64, MROWS/128);      // (12, 32)
    mma_gemm<<<ggrid, 256, GEMM_SMEM>>>(Mhi, Mlo, Wchi, Wclo, bp, out, nullptr, nullptr);
}

// round 14
// speedup vs baseline: 1.1289x; 1.0265x over previous
#include <cuda_runtime.h>
#include <cuda_bf16.h>

#define BD      2
#define SEQ     2048
#define DM      768
#define NH      12
#define DK      64
#define MROWS   (BD*SEQ)
#define ATT_SCALE 0.125f

typedef __nv_bfloat16 bf16;

// ===========================================================================
// helpers
// ===========================================================================
__device__ __forceinline__ unsigned smem_u32(const void* p) {
    unsigned a;
    asm("{ .reg .u64 t; cvta.to.shared.u64 t, %1; cvt.u32.u64 %0, t; }"
        : "=r"(a) : "l"(p));
    return a;
}
__device__ __forceinline__ void ldsm4(unsigned& r0, unsigned& r1, unsigned& r2,
                                      unsigned& r3, unsigned a) {
    asm volatile("ldmatrix.sync.aligned.m8n8.x4.shared.b16 {%0,%1,%2,%3}, [%4];"
        : "=r"(r0), "=r"(r1), "=r"(r2), "=r"(r3) : "r"(a));
}
__device__ __forceinline__ void ldsm4t(unsigned& r0, unsigned& r1, unsigned& r2,
                                       unsigned& r3, unsigned a) {
    asm volatile("ldmatrix.sync.aligned.m8n8.x4.trans.shared.b16 {%0,%1,%2,%3}, [%4];"
        : "=r"(r0), "=r"(r1), "=r"(r2), "=r"(r3) : "r"(a));
}
__device__ __forceinline__ void mma_bf16(float* c, const unsigned* a,
                                         unsigned b0, unsigned b1) {
    asm volatile("mma.sync.aligned.m16n8k16.row.col.f32.bf16.bf16.f32 "
        "{%0,%1,%2,%3},{%4,%5,%6,%7},{%8,%9},{%0,%1,%2,%3};"
        : "+f"(c[0]), "+f"(c[1]), "+f"(c[2]), "+f"(c[3])
        : "r"(a[0]), "r"(a[1]), "r"(a[2]), "r"(a[3]), "r"(b0), "r"(b1));
}
// hi/lo split using packed bf16x2 cvt (identical RN rounding, fewer ops)
__device__ __forceinline__ unsigned pack_hilo(float x, float y, unsigned& lo) {
    __nv_bfloat162 h2 = __floats2bfloat162_rn(x, y);   // .x=bf16(x) low, .y=bf16(y) high
    unsigned h = *reinterpret_cast<unsigned*>(&h2);
    float hx = __uint_as_float((h & 0xffffu) << 16);   // exact bf16->f32
    float hy = __uint_as_float(h & 0xffff0000u);
    __nv_bfloat162 l2 = __floats2bfloat162_rn(x - hx, y - hy);
    lo = *reinterpret_cast<unsigned*>(&l2);
    return h;
}
#define CPA16(d, s) \
    asm volatile("cp.async.cg.shared.global [%0], [%1], 16;" :: "r"(d), "l"(s) : "memory")
#define CP_COMMIT() asm volatile("cp.async.commit_group;" ::: "memory")
#define CP_WAIT1()  asm volatile("cp.async.wait_group 1;" ::: "memory")
#define CP_WAIT0()  asm volatile("cp.async.wait_group 0;" ::: "memory")

// ===========================================================================
// scratch
// ===========================================================================
__device__ bf16 g_xhi[MROWS*DM], g_xlo[MROWS*DM];
__device__ bf16 g_Whi[4*DM*DM],  g_Wlo[4*DM*DM];     // Wq, Wk, Wv, Wf
__device__ bf16 g_WoThi[DM*DM],  g_WoTlo[DM*DM];
__device__ bf16 g_Wchi[DM*DM],   g_Wclo[DM*DM];      // Wc = Wf @ Wo
__device__ bf16 g_Qhi[MROWS*DM], g_Qlo[MROWS*DM];
__device__ bf16 g_Khi[MROWS*DM], g_Klo[MROWS*DM];
__device__ bf16 g_Vhi[MROWS*DM], g_Vlo[MROWS*DM];
__device__ bf16 g_Mhi[MROWS*DM], g_Mlo[MROWS*DM];
__device__ float g_bp[DM];
__device__ float g_zb[DM];

// ===========================================================================
// merged prep kernel: hi/lo converts + Wo transpose + b' (one launch)
// ===========================================================================
#define N4X (MROWS*DM/4)
#define N4W (DM*DM/4)
#define NCVT ((N4X + 4*N4W + 255)/256)
#define NTRB (DM/32 * DM/32)
#define NBPB (DM/8)

__global__ void __launch_bounds__(256) prep_all(
    const float* __restrict__ x,
    const float* __restrict__ Wq, const float* __restrict__ Wk,
    const float* __restrict__ Wv, const float* __restrict__ Wf,
    const float* __restrict__ Wo, const float* __restrict__ bo,
    const float* __restrict__ bfv,
    bf16* __restrict__ xhi, bf16* __restrict__ xlo,
    bf16* __restrict__ Whi, bf16* __restrict__ Wlo,
    bf16* __restrict__ WoThi, bf16* __restrict__ WoTlo,
    float* __restrict__ bp)
{
    __shared__ float t[32][33];
    int b = blockIdx.x;
    if (b < NCVT) {
        int i = b * 256 + threadIdx.x;
        const float* src; bf16 *hi, *lo; int off;
        if (i < N4X) { src = x; hi = xhi; lo = xlo; off = i; }
        else {
            int j = i - N4X;
            if (j >= 4 * N4W) return;
            int w = j / N4W;
            off = j - w * N4W;
            src = (w == 0) ? Wq : (w == 1) ? Wk : (w == 2) ? Wv : Wf;
            hi = Whi + (size_t)w * (DM*DM);
            lo = Wlo + (size_t)w * (DM*DM);
        }
        float4 v = reinterpret_cast<const float4*>(src)[off];
        uint2 hp, lp;
        hp.x = pack_hilo(v.x, v.y, lp.x);
        hp.y = pack_hilo(v.z, v.w, lp.y);
        reinterpret_cast<uint2*>(hi)[off] = hp;
        reinterpret_cast<uint2*>(lo)[off] = lp;
    } else if (b < NCVT + NTRB) {
        int tb = b - NCVT;
        int bx = (tb % (DM/32)) * 32, by = (tb / (DM/32)) * 32;
        int tx = threadIdx.x & 31, ty = threadIdx.x >> 5;
        #pragma unroll
        for (int i = 0; i < 32; i += 8)
            t[ty + i][tx] = Wo[(size_t)(by + ty + i) * DM + bx + tx];
        __syncthreads();
        #pragma unroll
        for (int i = 0; i < 32; i += 8) {
            float v = t[tx][ty + i];
            bf16 h = __float2bfloat16(v);
            bf16 l = __float2bfloat16(v - __bfloat162float(h));
            size_t o = (size_t)(bx + ty + i) * DM + by + tx;
            WoThi[o] = h;
            WoTlo[o] = l;
        }
    } else {
        int nb = b - NCVT - NTRB;
        int n = nb * 8 + (threadIdx.x >> 5);
        int lane = threadIdx.x & 31;
        if (n >= DM) return;
        float s = 0.0f;
        for (int j = lane; j < DM; j += 32) s += Wf[(size_t)n * DM + j] * bo[j];
        #pragma unroll
        for (int o = 16; o > 0; o >>= 1) s += __shfl_xor_sync(0xffffffffu, s, o);
        if (lane == 0) bp[n] = s + bfv[n];
    }
}

// ===========================================================================
// GEMM (proven config): C = A @ W^T + bias, split-bf16 3-pass, cp.async
// 2-stage. Tile 128x64, K-chunk 64, 8 warps (4M x 2N), warp 32x32.
// ===========================================================================
#define GLD 72
#define G_AH_B 0
#define G_AL_B 18432
#define G_BH_B 36864
#define G_BL_B 46080
#define G_STAGE_B 55296
#define GEMM_SMEM (2*G_STAGE_B)

__device__ __forceinline__ void gemm_core(
    int row0, int col0,
    const bf16* __restrict__ Ahi, const bf16* __restrict__ Alo,
    const bf16* __restrict__ Bhi, const bf16* __restrict__ Blo,
    const float* __restrict__ bias,
    float* __restrict__ Cf, bf16* __restrict__ Chi, bf16* __restrict__ Clo)
{
    extern __shared__ char smc[];
    const int tid = threadIdx.x, lane = tid & 31, wid = tid >> 5;
    const int wm = wid >> 1, wn = wid & 1;
    const unsigned sb = smem_u32(smc);

    float acc[2][4][4];
    #pragma unroll
    for (int i = 0; i < 2; i++)
        #pragma unroll
        for (int j = 0; j < 4; j++)
            #pragma unroll
            for (int k = 0; k < 4; k++) acc[i][j][k] = 0.0f;

    auto issue = [&](int s, int kc) {
        unsigned stg = sb + s * G_STAGE_B;
        #pragma unroll
        for (int u = 0; u < 4; u++) {
            int idx = u * 256 + tid;
            int r = idx >> 3, c = idx & 7;
            const char* ga = (const char*)(Ahi + (size_t)(row0 + r) * DM + kc) + c * 16;
            const char* gl = (const char*)(Alo + (size_t)(row0 + r) * DM + kc) + c * 16;
            unsigned d = (unsigned)(r * GLD + c * 8) * 2;
            CPA16(stg + G_AH_B + d, ga);
            CPA16(stg + G_AL_B + d, gl);
        }
        #pragma unroll
        for (int u = 0; u < 2; u++) {
            int idx = u * 256 + tid;
            int r = idx >> 3, c = idx & 7;
            const char* gh = (const char*)(Bhi + (size_t)(col0 + r) * DM + kc) + c * 16;
            const char* gl = (const char*)(Blo + (size_t)(col0 + r) * DM + kc) + c * 16;
            unsigned d = (unsigned)(r * GLD + c * 8) * 2;
            CPA16(stg + G_BH_B + d, gh);
            CPA16(stg + G_BL_B + d, gl);
        }
    };

    issue(0, 0);
    CP_COMMIT();

    const int NC = DM / 64;   // 12
    for (int c = 0; c < NC; c++) {
        const int p = c & 1;
        CP_WAIT0();
        __syncthreads();
        if (c + 1 < NC) { issue(p ^ 1, (c + 1) * 64); CP_COMMIT(); }

        const unsigned stg = sb + p * G_STAGE_B;
        #pragma unroll
        for (int ks = 0; ks < 4; ks++) {
            const int kr = ks * 16;
            unsigned ah[2][4], al[2][4], bh[2][4], bl[2][4];
            #pragma unroll
            for (int mi = 0; mi < 2; mi++) {
                int m = wm * 32 + mi * 16 + (lane & 15);
                int kk = kr + (lane >> 4) * 8;
                ldsm4(ah[mi][0], ah[mi][1], ah[mi][2], ah[mi][3],
                      stg + G_AH_B + (m * GLD + kk) * 2);
                ldsm4(al[mi][0], al[mi][1], al[mi][2], al[mi][3],
                      stg + G_AL_B + (m * GLD + kk) * 2);
            }
            #pragma unroll
            for (int ni2 = 0; ni2 < 2; ni2++) {
                int n = wn * 32 + ni2 * 16 + (lane >> 4) * 8 + (lane & 7);
                int kk = kr + ((lane >> 3) & 1) * 8;
                ldsm4(bh[ni2][0], bh[ni2][1], bh[ni2][2], bh[ni2][3],
                      stg + G_BH_B + (n * GLD + kk) * 2);
                ldsm4(bl[ni2][0], bl[ni2][1], bl[ni2][2], bl[ni2][3],
                      stg + G_BL_B + (n * GLD + kk) * 2);
            }
            #pragma unroll
            for (int mi = 0; mi < 2; mi++)
                #pragma unroll
                for (int ni = 0; ni < 4; ni++) {
                    unsigned* bhp = &bh[ni >> 1][(ni & 1) * 2];
                    unsigned* blp = &bl[ni >> 1][(ni & 1) * 2];
                    mma_bf16(acc[mi][ni], ah[mi], bhp[0], bhp[1]);
                    mma_bf16(acc[mi][ni], ah[mi], blp[0], blp[1]);
                    mma_bf16(acc[mi][ni], al[mi], bhp[0], bhp[1]);
                }
        }
    }

    #pragma unroll
    for (int mi = 0; mi < 2; mi++)
        #pragma unroll
        for (int ni = 0; ni < 4; ni++) {
            int row = row0 + wm * 32 + mi * 16 + (lane >> 2);
            int col = col0 + wn * 32 + ni * 8 + (lane & 3) * 2;
            float2 bv = *reinterpret_cast<const float2*>(&bias[col]);
            #pragma unroll
            for (int h = 0; h < 2; h++) {
                int r = row + h * 8;
                float vx = acc[mi][ni][h * 2 + 0] + bv.x;
                float vy = acc[mi][ni][h * 2 + 1] + bv.y;
                size_t off = (size_t)r * DM + col;
                if (Cf) *reinterpret_cast<float2*>(&Cf[off]) = make_float2(vx, vy);
                if (Chi) {
                    unsigned lo, hi = pack_hilo(vx, vy, lo);
                    *reinterpret_cast<unsigned*>(&Chi[off]) = hi;
                    *reinterpret_cast<unsigned*>(&Clo[off]) = lo;
                }
            }
        }
}

// z = 0,1,2: QKV projections. z = 3 (first 6 y-blocks only): Wc = Wf @ Wo.
__global__ void __launch_bounds__(256, 2) qkv_gemm(
    const bf16* __restrict__ xhi, const bf16* __restrict__ xlo,
    const bf16* __restrict__ Whi, const bf16* __restrict__ Wlo,
    const bf16* __restrict__ WoThi, const bf16* __restrict__ WoTlo,
    const float* __restrict__ bq, const float* __restrict__ bk,
    const float* __restrict__ bv, const float* __restrict__ zb,
    bf16* __restrict__ Qhi, bf16* __restrict__ Qlo,
    bf16* __restrict__ Khi, bf16* __restrict__ Klo,
    bf16* __restrict__ Vhi, bf16* __restrict__ Vlo,
    bf16* __restrict__ Wchi, bf16* __restrict__ Wclo)
{
    const int z = blockIdx.z;
    const int WN = DM * DM;
    if (z == 3) {
        if (blockIdx.y >= DM / 128) return;
        gemm_core(blockIdx.y * 128, blockIdx.x * 64,
                  Whi + 3*(size_t)WN, Wlo + 3*(size_t)WN, WoThi, WoTlo,
                  zb, nullptr, Wchi, Wclo);
        return;
    }
    const float* bias = (z == 0) ? bq : (z == 1) ? bk : bv;
    bf16* Chi = (z == 0) ? Qhi : (z == 1) ? Khi : Vhi;
    bf16* Clo = (z == 0) ? Qlo : (z == 1) ? Klo : Vlo;
    gemm_core(blockIdx.y * 128, blockIdx.x * 64,
              xhi, xlo, Whi + (size_t)z * WN, Wlo + (size_t)z * WN, bias,
              nullptr, Chi, Clo);
}

// ===========================================================================
// Final GEMM: 64x64 tiles, 128 threads (2M x 2N warps), 3 CTAs/SM.
// FIXED loader: 512 vec16 per tile (4 iters x 128 threads, full 128B rows).
// ===========================================================================
#define H_T 9216                      // 64*GLD*2 bytes per tile
#define H_AH 0
#define H_AL (1*H_T)
#define H_BH (2*H_T)
#define H_BL (3*H_T)
#define H_STAGE (4*H_T)               // 36864
#define GEMM64_SMEM (2*H_STAGE)       // 73728

__global__ void __launch_bounds__(128, 3) gemm64(
    const bf16* __restrict__ Ahi, const bf16* __restrict__ Alo,
    const bf16* __restrict__ Bhi, const bf16* __restrict__ Blo,
    const float* __restrict__ bias, float* __restrict__ Cf)
{
    extern __shared__ char smc[];
    const int tid = threadIdx.x, lane = tid & 31, wid = tid >> 5;
    const int wm = wid >> 1, wn = wid & 1;
    const int row0 = blockIdx.y * 64, col0 = blockIdx.x * 64;
    const unsigned sb = smem_u32(smc);

    float acc[2][4][4];
    #pragma unroll
    for (int i = 0; i < 2; i++)
        #pragma unroll
        for (int j = 0; j < 4; j++)
            #pragma unroll
            for (int k = 0; k < 4; k++) acc[i][j][k] = 0.0f;

    auto issue = [&](int s, int kc) {
        unsigned stg = sb + s * H_STAGE;
        #pragma unroll
        for (int u = 0; u < 4; u++) {
            int idx = u * 128 + tid;          // 512 vec16 per tile
            int r = idx >> 3, c = idx & 7;    // full 8 x 16B per 64-bf16 row
            unsigned d = (unsigned)(r * GLD + c * 8) * 2;
            CPA16(stg + H_AH + d, (const char*)(Ahi + (size_t)(row0 + r) * DM + kc) + c * 16);
            CPA16(stg + H_AL + d, (const char*)(Alo + (size_t)(row0 + r) * DM + kc) + c * 16);
            CPA16(stg + H_BH + d, (const char*)(Bhi + (size_t)(col0 + r) * DM + kc) + c * 16);
            CPA16(stg + H_BL + d, (const char*)(Blo + (size_t)(col0 + r) * DM + kc) + c * 16);
        }
    };

    issue(0, 0);
    CP_COMMIT();

    const int NC = DM / 64;   // 12
    for (int c = 0; c < NC; c++) {
        const int p = c & 1;
        CP_WAIT0();
        __syncthreads();
        if (c + 1 < NC) { issue(p ^ 1, (c + 1) * 64); CP_COMMIT(); }

        const unsigned stg = sb + p * H_STAGE;
        #pragma unroll
        for (int ks = 0; ks < 4; ks++) {
            const int kr = ks * 16;
            unsigned ah[2][4], al[2][4], bh[2][4], bl[2][4];
            #pragma unroll
            for (int mi = 0; mi < 2; mi++) {
                int m = wm * 32 + mi * 16 + (lane & 15);
                int kk = kr + (lane >> 4) * 8;
                ldsm4(ah[mi][0], ah[mi][1], ah[mi][2], ah[mi][3],
                      stg + H_AH + (m * GLD + kk) * 2);
                ldsm4(al[mi][0], al[mi][1], al[mi][2], al[mi][3],
                      stg + H_AL + (m * GLD + kk) * 2);
            }
            #pragma unroll
            for (int ni2 = 0; ni2 < 2; ni2++) {
                int n = wn * 32 + ni2 * 16 + (lane >> 4) * 8 + (lane & 7);
                int kk = kr + ((lane >> 3) & 1) * 8;
                ldsm4(bh[ni2][0], bh[ni2][1], bh[ni2][2], bh[ni2][3],
                      stg + H_BH + (n * GLD + kk) * 2);
                ldsm4(bl[ni2][0], bl[ni2][1], bl[ni2][2], bl[ni2][3],
                      stg + H_BL + (n * GLD + kk) * 2);
            }
            #pragma unroll
            for (int mi = 0; mi < 2; mi++)
                #pragma unroll
                for (int ni = 0; ni < 4; ni++) {
                    unsigned* bhp = &bh[ni >> 1][(ni & 1) * 2];
                    unsigned* blp = &bl[ni >> 1][(ni & 1) * 2];
                    mma_bf16(acc[mi][ni], ah[mi], bhp[0], bhp[1]);
                    mma_bf16(acc[mi][ni], ah[mi], blp[0], blp[1]);
                    mma_bf16(acc[mi][ni], al[mi], bhp[0], bhp[1]);
                }
        }
    }

    #pragma unroll
    for (int mi = 0; mi < 2; mi++)
        #pragma unroll
        for (int ni = 0; ni < 4; ni++) {
            int row = row0 + wm * 32 + mi * 16 + (lane >> 2);
            int col = col0 + wn * 32 + ni * 8 + (lane & 3) * 2;
            float2 bv = *reinterpret_cast<const float2*>(&bias[col]);
            #pragma unroll
            for (int h = 0; h < 2; h++) {
                int r = row + h * 8;
                *reinterpret_cast<float2*>(&Cf[(size_t)r * DM + col]) =
                    make_float2(acc[mi][ni][h*2] + bv.x, acc[mi][ni][h*2+1] + bv.y);
            }
        }
}

// ===========================================================================
// Attention: 128 Q-rows/block, 8 warps, S register-resident, 3-stage cp.async
// K/V pipeline, Q fragments hoisted into registers.
// ===========================================================================
#define ALD 72
#define A_QH_B 0
#define A_QL_B 18432
#define A_STG_B 36864
#define A_STG_SZ 36864
#define A_KH_B 0
#define A_KL_B 9216
#define A_VH_B 18432
#define A_VL_B 27648
#define ATTN_SMEM (36864 + 3*A_STG_SZ)   // 147456
#define OLD 66

__global__ void __launch_bounds__(256) attn_mma(
    const bf16* __restrict__ Qhi, const bf16* __restrict__ Qlo,
    const bf16* __restrict__ Khi, const bf16* __restrict__ Klo,
    const bf16* __restrict__ Vhi, const bf16* __restrict__ Vlo,
    bf16* __restrict__ Mhi, bf16* __restrict__ Mlo)
{
    extern __shared__ char sma[];
    const int tid = threadIdx.x, lane = tid & 31, wid = tid >> 5;
    const int wm = wid >> 1, wn = wid & 1;
    const int bh = blockIdx.y;
    const int s0 = blockIdx.x * 128;
    const size_t base = (size_t)bh * SEQ * DK;
    const unsigned sb = smem_u32(sma);

    #pragma unroll
    for (int u = 0; u < 4; u++) {
        int idx = u * 256 + tid;
        int r = idx >> 3, c = idx & 7;
        size_t g = base + (size_t)(s0 + r) * DK + c * 8;
        *reinterpret_cast<uint4*>(sma + A_QH_B + (r * ALD + c * 8) * 2) =
            *reinterpret_cast<const uint4*>(Qhi + g);
        *reinterpret_cast<uint4*>(sma + A_QL_B + (r * ALD + c * 8) * 2) =
            *reinterpret_cast<const uint4*>(Qlo + g);
    }

    auto issue = [&](int s, int t0) {
        unsigned stg = sb + A_STG_B + s * A_STG_SZ;
        #pragma unroll
        for (int u = 0; u < 2; u++) {
            int idx = u * 256 + tid;
            int r = idx >> 3, c = idx & 7;
            size_t g = (base + (size_t)(t0 + r) * DK) * 2 + c * 16;
            unsigned d = (unsigned)(r * ALD + c * 8) * 2;
            CPA16(stg + A_KH_B + d, (const char*)Khi + g);
            CPA16(stg + A_KL_B + d, (const char*)Klo + g);
            CPA16(stg + A_VH_B + d, (const char*)Vhi + g);
            CPA16(stg + A_VL_B + d, (const char*)Vlo + g);
        }
    };

    issue(0, 0);
    CP_COMMIT();
    issue(1, 64);
    CP_COMMIT();

    __syncthreads();
    unsigned qh[4][2][4], ql[4][2][4];
    #pragma unroll
    for (int ks = 0; ks < 4; ks++)
        #pragma unroll
        for (int mi = 0; mi < 2; mi++) {
            int m = wm * 32 + mi * 16 + (lane & 15);
            int kk = ks * 16 + (lane >> 4) * 8;
            ldsm4(qh[ks][mi][0], qh[ks][mi][1], qh[ks][mi][2], qh[ks][mi][3],
                  sb + A_QH_B + (m * ALD + kk) * 2);
            ldsm4(ql[ks][mi][0], ql[ks][mi][1], ql[ks][mi][2], ql[ks][mi][3],
                  sb + A_QL_B + (m * ALD + kk) * 2);
        }

    float oacc[2][8][4];
    #pragma unroll
    for (int i = 0; i < 2; i++)
        #pragma unroll
        for (int j = 0; j < 8; j++)
            #pragma unroll
            for (int k = 0; k < 4; k++) oacc[i][j][k] = 0.0f;

    const int NC = SEQ / 64;   // 32
    int p = 0;
    for (int c = 0; c < NC; c++) {
        if (c + 1 < NC) { CP_WAIT1(); }
        else            { CP_WAIT0(); }
        __syncthreads();
        if (c + 2 < NC) { issue((p + 2) % 3, (c + 2) * 64); CP_COMMIT(); }

        const unsigned stg = sb + A_STG_B + p * A_STG_SZ;

        float sacc[2][4][4];
        #pragma unroll
        for (int i = 0; i < 2; i++)
            #pragma unroll
            for (int j = 0; j < 4; j++)
                #pragma unroll
                for (int k = 0; k < 4; k++) sacc[i][j][k] = 0.0f;

        #pragma unroll
        for (int ks = 0; ks < 4; ks++) {
            const int kr = ks * 16;
            unsigned bh_[2][4], bl_[2][4];
            #pragma unroll
            for (int ni2 = 0; ni2 < 2; ni2++) {
                int n = wn * 32 + ni2 * 16 + (lane >> 4) * 8 + (lane & 7);
                int kk = kr + ((lane >> 3) & 1) * 8;
                ldsm4(bh_[ni2][0], bh_[ni2][1], bh_[ni2][2], bh_[ni2][3],
                      stg + A_KH_B + (n * ALD + kk) * 2);
                ldsm4(bl_[ni2][0], bl_[ni2][1], bl_[ni2][2], bl_[ni2][3],
                      stg + A_KL_B + (n * ALD + kk) * 2);
            }
            #pragma unroll
            for (int mi = 0; mi < 2; mi++)
                #pragma unroll
                for (int ni = 0; ni < 4; ni++) {
                    unsigned* bhp = &bh_[ni >> 1][(ni & 1) * 2];
                    unsigned* blp = &bl_[ni >> 1][(ni & 1) * 2];
                    mma_bf16(sacc[mi][ni], qh[ks][mi], bhp[0], bhp[1]);
                    mma_bf16(sacc[mi][ni], qh[ks][mi], blp[0], blp[1]);
                    mma_bf16(sacc[mi][ni], ql[ks][mi], bhp[0], bhp[1]);
                }
        }

        #pragma unroll
        for (int j = 0; j < 2; j++) {
            unsigned sa_h[2][4], sa_l[2][4];
            #pragma unroll
            for (int mi = 0; mi < 2; mi++) {
                float* t0 = sacc[mi][2*j];
                float* t1 = sacc[mi][2*j + 1];
                sa_h[mi][0] = pack_hilo(t0[0]*ATT_SCALE, t0[1]*ATT_SCALE, sa_l[mi][0]);
                sa_h[mi][1] = pack_hilo(t0[2]*ATT_SCALE, t0[3]*ATT_SCALE, sa_l[mi][1]);
                sa_h[mi][2] = pack_hilo(t1[0]*ATT_SCALE, t1[1]*ATT_SCALE, sa_l[mi][2]);
                sa_h[mi][3] = pack_hilo(t1[2]*ATT_SCALE, t1[3]*ATT_SCALE, sa_l[mi][3]);
            }
            int kk = wn * 32 + j * 16 + (lane & 7) + ((lane >> 3) & 1) * 8;
            unsigned vh[4][4], vl[4][4];
            #pragma unroll
            for (int no2 = 0; no2 < 4; no2++) {
                int n = no2 * 16 + (lane >> 4) * 8;
                ldsm4t(vh[no2][0], vh[no2][1], vh[no2][2], vh[no2][3],
                       stg + A_VH_B + (kk * ALD + n) * 2);
                ldsm4t(vl[no2][0], vl[no2][1], vl[no2][2], vl[no2][3],
                       stg + A_VL_B + (kk * ALD + n) * 2);
            }
            #pragma unroll
            for (int mi = 0; mi < 2; mi++)
                #pragma unroll
                for (int no = 0; no < 8; no++) {
                    unsigned* bhp = &vh[no >> 1][(no & 1) * 2];
                    unsigned* blp = &vl[no >> 1][(no & 1) * 2];
                    mma_bf16(oacc[mi][no], sa_h[mi], bhp[0], bhp[1]);
                    mma_bf16(oacc[mi][no], sa_h[mi], blp[0], blp[1]);
                    mma_bf16(oacc[mi][no], sa_l[mi], bhp[0], bhp[1]);
                }
        }
        p = (p + 1) % 3;
    }

    __syncthreads();
    float* sOb = reinterpret_cast<float*>(sma + A_STG_B) + wn * (128 * OLD);
    #pragma unroll
    for (int mi = 0; mi < 2; mi++)
        #pragma unroll
        for (int no = 0; no < 8; no++) {
            int row = wm * 32 + mi * 16 + (lane >> 2);
            int col = no * 8 + (lane & 3) * 2;
            *reinterpret_cast<float2*>(&sOb[row * OLD + col]) =
                make_float2(oacc[mi][no][0], oacc[mi][no][1]);
            *reinterpret_cast<float2*>(&sOb[(row + 8) * OLD + col]) =
                make_float2(oacc[mi][no][2], oacc[mi][no][3]);
        }
    __syncthreads();

    float* p0buf = reinterpret_cast<float*>(sma + A_STG_B);
    float* p1buf = p0buf + 128 * OLD;
    #pragma unroll
    for (int i = 0; i < 16; i++) {
        int r = wid * 16 + i;
        float v0 = p0buf[r * OLD + lane]      + p1buf[r * OLD + lane];
        float v1 = p0buf[r * OLD + lane + 32] + p1buf[r * OLD + lane + 32];
        float mx = fmaxf(v0, v1);
        #pragma unroll
        for (int o = 16; o > 0; o >>= 1)
            mx = fmaxf(mx, __shfl_xor_sync(0xffffffffu, mx, o));
        float e0 = __expf(v0 - mx), e1 = __expf(v1 - mx);
        float s = e0 + e1;
        #pragma unroll
        for (int o = 16; o > 0; o >>= 1) s += __shfl_xor_sync(0xffffffffu, s, o);
        float inv = 1.0f / s;
        float q0 = e0 * inv, q1 = e1 * inv;
        size_t g = base + (size_t)(s0 + r) * DK;
        bf16 h0 = __float2bfloat16(q0), h1 = __float2bfloat16(q1);
        Mhi[g + lane]      = h0;
        Mhi[g + lane + 32] = h1;
        Mlo[g + lane]      = __float2bfloat16(q0 - __bfloat162float(h0));
        Mlo[g + lane + 32] = __float2bfloat16(q1 - __bfloat162float(h1));
    }
}

// ===========================================================================
// Launch
// ===========================================================================
extern "C" void kernel_launch(void* const* d_in, const int* in_sizes, int n_in,
                              void* d_out, int out_size)
{
    const float* x  = (const float*)d_in[0];
    const float* Wq = (const float*)d_in[1];
    const float* bq = (const float*)d_in[2];
    const float* Wk = (const float*)d_in[3];
    const float* bk = (const float*)d_in[4];
    const float* Wv = (const float*)d_in[5];
    const float* bv = (const float*)d_in[6];
    const float* Wo = (const float*)d_in[7];
    const float* bo = (const float*)d_in[8];
    const float* Wf = (const float*)d_in[9];
    const float* bf_ = (const float*)d_in[10];
    float* out = (float*)d_out;

    bf16 *xhi, *xlo, *Whi, *Wlo, *WoThi, *WoTlo, *Wchi, *Wclo;
    bf16 *Qhi, *Qlo, *Khi, *Klo, *Vhi, *Vlo, *Mhi, *Mlo;
    float *bp, *zb;
    cudaGetSymbolAddress((void**)&xhi, g_xhi); cudaGetSymbolAddress((void**)&xlo, g_xlo);
    cudaGetSymbolAddress((void**)&Whi, g_Whi); cudaGetSymbolAddress((void**)&Wlo, g_Wlo);
    cudaGetSymbolAddress((void**)&WoThi, g_WoThi); cudaGetSymbolAddress((void**)&WoTlo, g_WoTlo);
    cudaGetSymbolAddress((void**)&Wchi, g_Wchi); cudaGetSymbolAddress((void**)&Wclo, g_Wclo);
    cudaGetSymbolAddress((void**)&Qhi, g_Qhi); cudaGetSymbolAddress((void**)&Qlo, g_Qlo);
    cudaGetSymbolAddress((void**)&Khi, g_Khi); cudaGetSymbolAddress((void**)&Klo, g_Klo);
    cudaGetSymbolAddress((void**)&Vhi, g_Vhi); cudaGetSymbolAddress((void**)&Vlo, g_Vlo);
    cudaGetSymbolAddress((void**)&Mhi, g_Mhi); cudaGetSymbolAddress((void**)&Mlo, g_Mlo);
    cudaGetSymbolAddress((void**)&bp, g_bp); cudaGetSymbolAddress((void**)&zb, g_zb);

    cudaFuncSetAttribute(qkv_gemm, cudaFuncAttributeMaxDynamicSharedMemorySize, GEMM_SMEM);
    cudaFuncSetAttribute(gemm64, cudaFuncAttributeMaxDynamicSharedMemorySize, GEMM64_SMEM);
    cudaFuncSetAttribute(attn_mma, cudaFuncAttributeMaxDynamicSharedMemorySize, ATTN_SMEM);

    // one prep launch: converts + Wo transpose + b'
    prep_all<<<NCVT + NTRB + NBPB, 256>>>(x, Wq, Wk, Wv, Wf, Wo, bo, bf_,
                                          xhi, xlo, Whi, Wlo, WoThi, WoTlo, bp);

    // QKV projections + Wc = Wf@Wo folded in as z=3 (y<6 active)
    dim3 qgrid(DM/64, MROWS/128, 4);   // (12, 32, 4)
    qkv_gemm<<<qgrid, 256, GEMM_SMEM>>>(xhi, xlo, Whi, Wlo, WoThi, WoTlo,
                                        bq, bk, bv, zb,
                                        Qhi, Qlo, Khi, Klo, Vhi, Vlo,
                                        Wchi, Wclo);

    // attention (fused softmax -> M hi/lo)
    dim3 agrid(SEQ/128, BD*NH);        // (16, 24)
    attn_mma<<<agrid, 256, ATTN_SMEM>>>(Qhi, Qlo, Khi, Klo, Vhi, Vlo, Mhi, Mlo);

    // single fused output projection: out = M @ Wc^T + b' (64x64 tiles)
    dim3 ggrid(DM/64, MROWS/64);       // (12, 64) = 768 blocks
    gemm64<<<ggrid, 128, GEMM64_SMEM>>>(Mhi, Mlo, Wchi, Wclo, bp, out);
}

// round 15
// speedup vs baseline: 2.1039x; 1.8637x over previous
#include <cuda_runtime.h>
#include <cuda_bf16.h>

#define BD      2
#define SEQ     2048
#define DM      768
#define NH      12
#define DK      64
#define MROWS   (BD*SEQ)
#define ATT_SCALE 0.125f
#define NHEADS  (BD*NH)      // 24
#define NSPLIT  4

typedef __nv_bfloat16 bf16;

// ===========================================================================
// helpers
// ===========================================================================
__device__ __forceinline__ unsigned smem_u32(const void* p) {
    unsigned a;
    asm("{ .reg .u64 t; cvta.to.shared.u64 t, %1; cvt.u32.u64 %0, t; }"
        : "=r"(a) : "l"(p));
    return a;
}
__device__ __forceinline__ void ldsm4(unsigned& r0, unsigned& r1, unsigned& r2,
                                      unsigned& r3, unsigned a) {
    asm volatile("ldmatrix.sync.aligned.m8n8.x4.shared.b16 {%0,%1,%2,%3}, [%4];"
        : "=r"(r0), "=r"(r1), "=r"(r2), "=r"(r3) : "r"(a));
}
__device__ __forceinline__ void ldsm4t(unsigned& r0, unsigned& r1, unsigned& r2,
                                       unsigned& r3, unsigned a) {
    asm volatile("ldmatrix.sync.aligned.m8n8.x4.trans.shared.b16 {%0,%1,%2,%3}, [%4];"
        : "=r"(r0), "=r"(r1), "=r"(r2), "=r"(r3) : "r"(a));
}
__device__ __forceinline__ void mma_bf16(float* c, const unsigned* a,
                                         unsigned b0, unsigned b1) {
    asm volatile("mma.sync.aligned.m16n8k16.row.col.f32.bf16.bf16.f32 "
        "{%0,%1,%2,%3},{%4,%5,%6,%7},{%8,%9},{%0,%1,%2,%3};"
        : "+f"(c[0]), "+f"(c[1]), "+f"(c[2]), "+f"(c[3])
        : "r"(a[0]), "r"(a[1]), "r"(a[2]), "r"(a[3]), "r"(b0), "r"(b1));
}
__device__ __forceinline__ unsigned pack_hilo(float x, float y, unsigned& lo) {
    __nv_bfloat162 h2 = __floats2bfloat162_rn(x, y);
    unsigned h = *reinterpret_cast<unsigned*>(&h2);
    float hx = __uint_as_float((h & 0xffffu) << 16);
    float hy = __uint_as_float(h & 0xffff0000u);
    __nv_bfloat162 l2 = __floats2bfloat162_rn(x - hx, y - hy);
    lo = *reinterpret_cast<unsigned*>(&l2);
    return h;
}
#define CPA16(d, s) \
    asm volatile("cp.async.cg.shared.global [%0], [%1], 16;" :: "r"(d), "l"(s) : "memory")
#define CP_COMMIT() asm volatile("cp.async.commit_group;" ::: "memory")
#define CP_WAIT0()  asm volatile("cp.async.wait_group 0;" ::: "memory")

// ===========================================================================
// scratch
// ===========================================================================
__device__ bf16 g_xhi[MROWS*DM], g_xlo[MROWS*DM];
__device__ bf16 g_Whi[4*DM*DM],  g_Wlo[4*DM*DM];
__device__ bf16 g_WoThi[DM*DM],  g_WoTlo[DM*DM];
__device__ bf16 g_Wchi[DM*DM],   g_Wclo[DM*DM];
__device__ bf16 g_Qhi[MROWS*DM], g_Qlo[MROWS*DM];
__device__ bf16 g_Khi[MROWS*DM], g_Klo[MROWS*DM];
__device__ bf16 g_Vhi[MROWS*DM], g_Vlo[MROWS*DM];
__device__ bf16 g_Mhi[MROWS*DM], g_Mlo[MROWS*DM];
__device__ float g_Tp[NHEADS*NSPLIT*DK*DK];    // K^T V partials
__device__ float g_bp[DM];
__device__ float g_zb[DM];

// ===========================================================================
// merged prep kernel: hi/lo converts + Wo transpose + b'
// ===========================================================================
#define N4X (MROWS*DM/4)
#define N4W (DM*DM/4)
#define NCVT ((N4X + 4*N4W + 255)/256)
#define NTRB (DM/32 * DM/32)
#define NBPB (DM/8)

__global__ void __launch_bounds__(256) prep_all(
    const float* __restrict__ x,
    const float* __restrict__ Wq, const float* __restrict__ Wk,
    const float* __restrict__ Wv, const float* __restrict__ Wf,
    const float* __restrict__ Wo, const float* __restrict__ bo,
    const float* __restrict__ bfv,
    bf16* __restrict__ xhi, bf16* __restrict__ xlo,
    bf16* __restrict__ Whi, bf16* __restrict__ Wlo,
    bf16* __restrict__ WoThi, bf16* __restrict__ WoTlo,
    float* __restrict__ bp)
{
    __shared__ float t[32][33];
    int b = blockIdx.x;
    if (b < NCVT) {
        int i = b * 256 + threadIdx.x;
        const float* src; bf16 *hi, *lo; int off;
        if (i < N4X) { src = x; hi = xhi; lo = xlo; off = i; }
        else {
            int j = i - N4X;
            if (j >= 4 * N4W) return;
            int w = j / N4W;
            off = j - w * N4W;
            src = (w == 0) ? Wq : (w == 1) ? Wk : (w == 2) ? Wv : Wf;
            hi = Whi + (size_t)w * (DM*DM);
            lo = Wlo + (size_t)w * (DM*DM);
        }
        float4 v = reinterpret_cast<const float4*>(src)[off];
        uint2 hp, lp;
        hp.x = pack_hilo(v.x, v.y, lp.x);
        hp.y = pack_hilo(v.z, v.w, lp.y);
        reinterpret_cast<uint2*>(hi)[off] = hp;
        reinterpret_cast<uint2*>(lo)[off] = lp;
    } else if (b < NCVT + NTRB) {
        int tb = b - NCVT;
        int bx = (tb % (DM/32)) * 32, by = (tb / (DM/32)) * 32;
        int tx = threadIdx.x & 31, ty = threadIdx.x >> 5;
        #pragma unroll
        for (int i = 0; i < 32; i += 8)
            t[ty + i][tx] = Wo[(size_t)(by + ty + i) * DM + bx + tx];
        __syncthreads();
        #pragma unroll
        for (int i = 0; i < 32; i += 8) {
            float v = t[tx][ty + i];
            bf16 h = __float2bfloat16(v);
            bf16 l = __float2bfloat16(v - __bfloat162float(h));
            size_t o = (size_t)(bx + ty + i) * DM + by + tx;
            WoThi[o] = h;
            WoTlo[o] = l;
        }
    } else {
        int nb = b - NCVT - NTRB;
        int n = nb * 8 + (threadIdx.x >> 5);
        int lane = threadIdx.x & 31;
        if (n >= DM) return;
        float s = 0.0f;
        for (int j = lane; j < DM; j += 32) s += Wf[(size_t)n * DM + j] * bo[j];
        #pragma unroll
        for (int o = 16; o > 0; o >>= 1) s += __shfl_xor_sync(0xffffffffu, s, o);
        if (lane == 0) bp[n] = s + bfv[n];
    }
}

// ===========================================================================
// GEMM (proven config): C = A @ W^T + bias, split-bf16 3-pass, cp.async
// 2-stage. Tile 128x64, K-chunk 64, 8 warps (4M x 2N), warp 32x32.
// ===========================================================================
#define GLD 72
#define G_AH_B 0
#define G_AL_B 18432
#define G_BH_B 36864
#define G_BL_B 46080
#define G_STAGE_B 55296
#define GEMM_SMEM (2*G_STAGE_B)

__device__ __forceinline__ void gemm_core(
    int row0, int col0,
    const bf16* __restrict__ Ahi, const bf16* __restrict__ Alo,
    const bf16* __restrict__ Bhi, const bf16* __restrict__ Blo,
    const float* __restrict__ bias,
    float* __restrict__ Cf, bf16* __restrict__ Chi, bf16* __restrict__ Clo)
{
    extern __shared__ char smc[];
    const int tid = threadIdx.x, lane = tid & 31, wid = tid >> 5;
    const int wm = wid >> 1, wn = wid & 1;
    const unsigned sb = smem_u32(smc);

    float acc[2][4][4];
    #pragma unroll
    for (int i = 0; i < 2; i++)
        #pragma unroll
        for (int j = 0; j < 4; j++)
            #pragma unroll
            for (int k = 0; k < 4; k++) acc[i][j][k] = 0.0f;

    auto issue = [&](int s, int kc) {
        unsigned stg = sb + s * G_STAGE_B;
        #pragma unroll
        for (int u = 0; u < 4; u++) {
            int idx = u * 256 + tid;
            int r = idx >> 3, c = idx & 7;
            unsigned d = (unsigned)(r * GLD + c * 8) * 2;
            CPA16(stg + G_AH_B + d, (const char*)(Ahi + (size_t)(row0 + r) * DM + kc) + c * 16);
            CPA16(stg + G_AL_B + d, (const char*)(Alo + (size_t)(row0 + r) * DM + kc) + c * 16);
        }
        #pragma unroll
        for (int u = 0; u < 2; u++) {
            int idx = u * 256 + tid;
            int r = idx >> 3, c = idx & 7;
            unsigned d = (unsigned)(r * GLD + c * 8) * 2;
            CPA16(stg + G_BH_B + d, (const char*)(Bhi + (size_t)(col0 + r) * DM + kc) + c * 16);
            CPA16(stg + G_BL_B + d, (const char*)(Blo + (size_t)(col0 + r) * DM + kc) + c * 16);
        }
    };

    issue(0, 0);
    CP_COMMIT();

    const int NC = DM / 64;   // 12
    for (int c = 0; c < NC; c++) {
        const int p = c & 1;
        CP_WAIT0();
        __syncthreads();
        if (c + 1 < NC) { issue(p ^ 1, (c + 1) * 64); CP_COMMIT(); }

        const unsigned stg = sb + p * G_STAGE_B;
        #pragma unroll
        for (int ks = 0; ks < 4; ks++) {
            const int kr = ks * 16;
            unsigned ah[2][4], al[2][4], bh[2][4], bl[2][4];
            #pragma unroll
            for (int mi = 0; mi < 2; mi++) {
                int m = wm * 32 + mi * 16 + (lane & 15);
                int kk = kr + (lane >> 4) * 8;
                ldsm4(ah[mi][0], ah[mi][1], ah[mi][2], ah[mi][3],
                      stg + G_AH_B + (m * GLD + kk) * 2);
                ldsm4(al[mi][0], al[mi][1], al[mi][2], al[mi][3],
                      stg + G_AL_B + (m * GLD + kk) * 2);
            }
            #pragma unroll
            for (int ni2 = 0; ni2 < 2; ni2++) {
                int n = wn * 32 + ni2 * 16 + (lane >> 4) * 8 + (lane & 7);
                int kk = kr + ((lane >> 3) & 1) * 8;
                ldsm4(bh[ni2][0], bh[ni2][1], bh[ni2][2], bh[ni2][3],
                      stg + G_BH_B + (n * GLD + kk) * 2);
                ldsm4(bl[ni2][0], bl[ni2][1], bl[ni2][2], bl[ni2][3],
                      stg + G_BL_B + (n * GLD + kk) * 2);
            }
            #pragma unroll
            for (int mi = 0; mi < 2; mi++)
                #pragma unroll
                for (int ni = 0; ni < 4; ni++) {
                    unsigned* bhp = &bh[ni >> 1][(ni & 1) * 2];
                    unsigned* blp = &bl[ni >> 1][(ni & 1) * 2];
                    mma_bf16(acc[mi][ni], ah[mi], bhp[0], bhp[1]);
                    mma_bf16(acc[mi][ni], ah[mi], blp[0], blp[1]);
                    mma_bf16(acc[mi][ni], al[mi], bhp[0], bhp[1]);
                }
        }
    }

    #pragma unroll
    for (int mi = 0; mi < 2; mi++)
        #pragma unroll
        for (int ni = 0; ni < 4; ni++) {
            int row = row0 + wm * 32 + mi * 16 + (lane >> 2);
            int col = col0 + wn * 32 + ni * 8 + (lane & 3) * 2;
            float2 bv = *reinterpret_cast<const float2*>(&bias[col]);
            #pragma unroll
            for (int h = 0; h < 2; h++) {
                int r = row + h * 8;
                float vx = acc[mi][ni][h * 2 + 0] + bv.x;
                float vy = acc[mi][ni][h * 2 + 1] + bv.y;
                size_t off = (size_t)r * DM + col;
                if (Cf) *reinterpret_cast<float2*>(&Cf[off]) = make_float2(vx, vy);
                if (Chi) {
                    unsigned lo, hi = pack_hilo(vx, vy, lo);
                    *reinterpret_cast<unsigned*>(&Chi[off]) = hi;
                    *reinterpret_cast<unsigned*>(&Clo[off]) = lo;
                }
            }
        }
}

// z = 0,1,2: QKV projections. z = 3 (first 6 y-blocks only): Wc = Wf @ Wo.
__global__ void __launch_bounds__(256, 2) qkv_gemm(
    const bf16* __restrict__ xhi, const bf16* __restrict__ xlo,
    const bf16* __restrict__ Whi, const bf16* __restrict__ Wlo,
    const bf16* __restrict__ WoThi, const bf16* __restrict__ WoTlo,
    const float* __restrict__ bq, const float* __restrict__ bk,
    const float* __restrict__ bv, const float* __restrict__ zb,
    bf16* __restrict__ Qhi, bf16* __restrict__ Qlo,
    bf16* __restrict__ Khi, bf16* __restrict__ Klo,
    bf16* __restrict__ Vhi, bf16* __restrict__ Vlo,
    bf16* __restrict__ Wchi, bf16* __restrict__ Wclo)
{
    const int z = blockIdx.z;
    const int WN = DM * DM;
    if (z == 3) {
        if (blockIdx.y >= DM / 128) return;
        gemm_core(blockIdx.y * 128, blockIdx.x * 64,
                  Whi + 3*(size_t)WN, Wlo + 3*(size_t)WN, WoThi, WoTlo,
                  zb, nullptr, Wchi, Wclo);
        return;
    }
    const float* bias = (z == 0) ? bq : (z == 1) ? bk : bv;
    bf16* Chi = (z == 0) ? Qhi : (z == 1) ? Khi : Vhi;
    bf16* Clo = (z == 0) ? Qlo : (z == 1) ? Klo : Vlo;
    gemm_core(blockIdx.y * 128, blockIdx.x * 64,
              xhi, xlo, Whi + (size_t)z * WN, Wlo + (size_t)z * WN, bias,
              nullptr, Chi, Clo);
}

// ===========================================================================
// Final GEMM: 64x64 tiles, 128 threads, 3 CTAs/SM.
// ===========================================================================
#define H_T 9216
#define H_AH 0
#define H_AL (1*H_T)
#define H_BH (2*H_T)
#define H_BL (3*H_T)
#define H_STAGE (4*H_T)
#define GEMM64_SMEM (2*H_STAGE)

__global__ void __launch_bounds__(128, 3) gemm64(
    const bf16* __restrict__ Ahi, const bf16* __restrict__ Alo,
    const bf16* __restrict__ Bhi, const bf16* __restrict__ Blo,
    const float* __restrict__ bias, float* __restrict__ Cf)
{
    extern __shared__ char smc[];
    const int tid = threadIdx.x, lane = tid & 31, wid = tid >> 5;
    const int wm = wid >> 1, wn = wid & 1;
    const int row0 = blockIdx.y * 64, col0 = blockIdx.x * 64;
    const unsigned sb = smem_u32(smc);

    float acc[2][4][4];
    #pragma unroll
    for (int i = 0; i < 2; i++)
        #pragma unroll
        for (int j = 0; j < 4; j++)
            #pragma unroll
            for (int k = 0; k < 4; k++) acc[i][j][k] = 0.0f;

    auto issue = [&](int s, int kc) {
        unsigned stg = sb + s * H_STAGE;
        #pragma unroll
        for (int u = 0; u < 4; u++) {
            int idx = u * 128 + tid;
            int r = idx >> 3, c = idx & 7;
            unsigned d = (unsigned)(r * GLD + c * 8) * 2;
            CPA16(stg + H_AH + d, (const char*)(Ahi + (size_t)(row0 + r) * DM + kc) + c * 16);
            CPA16(stg + H_AL + d, (const char*)(Alo + (size_t)(row0 + r) * DM + kc) + c * 16);
            CPA16(stg + H_BH + d, (const char*)(Bhi + (size_t)(col0 + r) * DM + kc) + c * 16);
            CPA16(stg + H_BL + d, (const char*)(Blo + (size_t)(col0 + r) * DM + kc) + c * 16);
        }
    };

    issue(0, 0);
    CP_COMMIT();

    const int NC = DM / 64;   // 12
    for (int c = 0; c < NC; c++) {
        const int p = c & 1;
        CP_WAIT0();
        __syncthreads();
        if (c + 1 < NC) { issue(p ^ 1, (c + 1) * 64); CP_COMMIT(); }

        const unsigned stg = sb + p * H_STAGE;
        #pragma unroll
        for (int ks = 0; ks < 4; ks++) {
            const int kr = ks * 16;
            unsigned ah[2][4], al[2][4], bh[2][4], bl[2][4];
            #pragma unroll
            for (int mi = 0; mi < 2; mi++) {
                int m = wm * 32 + mi * 16 + (lane & 15);
                int kk = kr + (lane >> 4) * 8;
                ldsm4(ah[mi][0], ah[mi][1], ah[mi][2], ah[mi][3],
                      stg + H_AH + (m * GLD + kk) * 2);
                ldsm4(al[mi][0], al[mi][1], al[mi][2], al[mi][3],
                      stg + H_AL + (m * GLD + kk) * 2);
            }
            #pragma unroll
            for (int ni2 = 0; ni2 < 2; ni2++) {
                int n = wn * 32 + ni2 * 16 + (lane >> 4) * 8 + (lane & 7);
                int kk = kr + ((lane >> 3) & 1) * 8;
                ldsm4(bh[ni2][0], bh[ni2][1], bh[ni2][2], bh[ni2][3],
                      stg + H_BH + (n * GLD + kk) * 2);
                ldsm4(bl[ni2][0], bl[ni2][1], bl[ni2][2], bl[ni2][3],
                      stg + H_BL + (n * GLD + kk) * 2);
            }
            #pragma unroll
            for (int mi = 0; mi < 2; mi++)
                #pragma unroll
                for (int ni = 0; ni < 4; ni++) {
                    unsigned* bhp = &bh[ni >> 1][(ni & 1) * 2];
                    unsigned* blp = &bl[ni >> 1][(ni & 1) * 2];
                    mma_bf16(acc[mi][ni], ah[mi], bhp[0], bhp[1]);
                    mma_bf16(acc[mi][ni], ah[mi], blp[0], blp[1]);
                    mma_bf16(acc[mi][ni], al[mi], bhp[0], bhp[1]);
                }
        }
    }

    #pragma unroll
    for (int mi = 0; mi < 2; mi++)
        #pragma unroll
        for (int ni = 0; ni < 4; ni++) {
            int row = row0 + wm * 32 + mi * 16 + (lane >> 2);
            int col = col0 + wn * 32 + ni * 8 + (lane & 3) * 2;
            float2 bv = *reinterpret_cast<const float2*>(&bias[col]);
            #pragma unroll
            for (int h = 0; h < 2; h++) {
                int r = row + h * 8;
                *reinterpret_cast<float2*>(&Cf[(size_t)r * DM + col]) =
                    make_float2(acc[mi][ni][h*2] + bv.x, acc[mi][ni][h*2+1] + bv.y);
            }
        }
}

// ===========================================================================
// ktv_kernel: partial T = K^T V per (head, t-split of 512). Output fp32.
// 8 warps: wm 0-3 (d1 16 rows), wn 0-1 (d2 32 cols). A = K^T via ldsm4t.
// ===========================================================================
#define ALD 72
#define KV_KH 0
#define KV_KL 9216
#define KV_VH 18432
#define KV_VL 27648
#define KV_STAGE 36864
#define KTV_SMEM (2*KV_STAGE)   // 73728

__global__ void __launch_bounds__(256, 2) ktv_kernel(
    const bf16* __restrict__ Khi, const bf16* __restrict__ Klo,
    const bf16* __restrict__ Vhi, const bf16* __restrict__ Vlo,
    float* __restrict__ Tp)
{
    extern __shared__ char smk[];
    const int tid = threadIdx.x, lane = tid & 31, wid = tid >> 5;
    const int wm = wid >> 1, wn = wid & 1;
    const int head = blockIdx.y, split = blockIdx.x;
    const size_t base = (size_t)head * SEQ * DK;
    const int tb0 = split * (SEQ / NSPLIT);        // 512-range start
    const unsigned sb = smem_u32(smk);

    auto issue = [&](int s, int t0) {
        unsigned stg = sb + s * KV_STAGE;
        #pragma unroll
        for (int u = 0; u < 2; u++) {
            int idx = u * 256 + tid;
            int r = idx >> 3, c = idx & 7;
            size_t g = (base + (size_t)(t0 + r) * DK) * 2 + c * 16;
            unsigned d = (unsigned)(r * ALD + c * 8) * 2;
            CPA16(stg + KV_KH + d, (const char*)Khi + g);
            CPA16(stg + KV_KL + d, (const char*)Klo + g);
            CPA16(stg + KV_VH + d, (const char*)Vhi + g);
            CPA16(stg + KV_VL + d, (const char*)Vlo + g);
        }
    };

    float acc[4][4];
    #pragma unroll
    for (int j = 0; j < 4; j++)
        #pragma unroll
        for (int k = 0; k < 4; k++) acc[j][k] = 0.0f;

    issue(0, tb0);
    CP_COMMIT();

    const int NC = (SEQ / NSPLIT) / 64;   // 8 chunks
    for (int c = 0; c < NC; c++) {
        const int p = c & 1;
        CP_WAIT0();
        __syncthreads();
        if (c + 1 < NC) { issue(p ^ 1, tb0 + (c + 1) * 64); CP_COMMIT(); }

        const unsigned stg = sb + p * KV_STAGE;
        #pragma unroll
        for (int ks = 0; ks < 4; ks++) {
            // A = K^T fragments: row = t, col = d1 (trans load)
            int trow = ks * 16 + (lane & 7) + ((lane >> 4) & 1) * 8;
            int dcol = wm * 16 + ((lane >> 3) & 1) * 8;
            unsigned ah[4], al[4];
            ldsm4t(ah[0], ah[1], ah[2], ah[3],
                   stg + KV_KH + (trow * ALD + dcol) * 2);
            ldsm4t(al[0], al[1], al[2], al[3],
                   stg + KV_KL + (trow * ALD + dcol) * 2);
            // B = V fragments (contraction over t), same as attention S@V
            int kk = ks * 16 + (lane & 7) + ((lane >> 3) & 1) * 8;
            unsigned vh[2][4], vl[2][4];
            #pragma unroll
            for (int no2 = 0; no2 < 2; no2++) {
                int n = wn * 32 + no2 * 16 + (lane >> 4) * 8;
                ldsm4t(vh[no2][0], vh[no2][1], vh[no2][2], vh[no2][3],
                       stg + KV_VH + (kk * ALD + n) * 2);
                ldsm4t(vl[no2][0], vl[no2][1], vl[no2][2], vl[no2][3],
                       stg + KV_VL + (kk * ALD + n) * 2);
            }
            #pragma unroll
            for (int no = 0; no < 4; no++) {
                unsigned* bhp = &vh[no >> 1][(no & 1) * 2];
                unsigned* blp = &vl[no >> 1][(no & 1) * 2];
                mma_bf16(acc[no], ah, bhp[0], bhp[1]);
                mma_bf16(acc[no], ah, blp[0], blp[1]);
                mma_bf16(acc[no], al, bhp[0], bhp[1]);
            }
        }
    }

    // write partial T (fp32, row-major [d1][d2])
    float* dst = Tp + ((size_t)head * NSPLIT + split) * (DK * DK);
    #pragma unroll
    for (int no = 0; no < 4; no++) {
        int r = wm * 16 + (lane >> 2);
        int cc = wn * 32 + no * 8 + (lane & 3) * 2;
        *reinterpret_cast<float2*>(&dst[r * DK + cc]) =
            make_float2(acc[no][0], acc[no][1]);
        *reinterpret_cast<float2*>(&dst[(r + 8) * DK + cc]) =
            make_float2(acc[no][2], acc[no][3]);
    }
}

// ===========================================================================
// qt_softmax: O = Q @ (SCALE * T), then softmax over dk=64 -> M hi/lo.
// 128 Q-rows per block, 8 warps (wm 0-3 x wn 0-1), one K=64 chunk.
// ===========================================================================
#define QT_TH 0
#define QT_TL 9216
#define QT_QH 18432
#define QT_QL 36864
#define QT_O  18432                 // fp32 overlay on Q region after MMA
#define QT_SMEM 55296
#define OLD 66

__global__ void __launch_bounds__(256) qt_softmax(
    const bf16* __restrict__ Qhi, const bf16* __restrict__ Qlo,
    const float* __restrict__ Tp,
    bf16* __restrict__ Mhi, bf16* __restrict__ Mlo)
{
    extern __shared__ char smq[];
    const int tid = threadIdx.x, lane = tid & 31, wid = tid >> 5;
    const int wm = wid >> 1, wn = wid & 1;
    const int head = blockIdx.y;
    const int s0 = blockIdx.x * 128;
    const size_t base = (size_t)head * SEQ * DK;
    const unsigned sb = smem_u32(smq);

    // reduce 4 partials -> T, scale, pack hi/lo into smem
    {
        const float4* tp = reinterpret_cast<const float4*>(
            Tp + (size_t)head * NSPLIT * (DK * DK));
        #pragma unroll
        for (int i = tid; i < (DK * DK) / 4; i += 256) {   // 1024 float4
            float4 a = tp[i];
            float4 b = tp[1024 + i];
            float4 cc = tp[2048 + i];
            float4 d = tp[3072 + i];
            float v0 = (a.x + b.x + cc.x + d.x) * ATT_SCALE;
            float v1 = (a.y + b.y + cc.y + d.y) * ATT_SCALE;
            float v2 = (a.z + b.z + cc.z + d.z) * ATT_SCALE;
            float v3 = (a.w + b.w + cc.w + d.w) * ATT_SCALE;
            uint2 hp, lp;
            hp.x = pack_hilo(v0, v1, lp.x);
            hp.y = pack_hilo(v2, v3, lp.y);
            int e = i * 4, r = e >> 6, col = e & 63;
            *reinterpret_cast<uint2*>(smq + QT_TH + (r * ALD + col) * 2) = hp;
            *reinterpret_cast<uint2*>(smq + QT_TL + (r * ALD + col) * 2) = lp;
        }
    }
    // load Q tile (128x64 hi/lo)
    #pragma unroll
    for (int u = 0; u < 4; u++) {
        int idx = u * 256 + tid;
        int r = idx >> 3, c = idx & 7;
        size_t g = base + (size_t)(s0 + r) * DK + c * 8;
        *reinterpret_cast<uint4*>(smq + QT_QH + (r * ALD + c * 8) * 2) =
            *reinterpret_cast<const uint4*>(Qhi + g);
        *reinterpret_cast<uint4*>(smq + QT_QL + (r * ALD + c * 8) * 2) =
            *reinterpret_cast<const uint4*>(Qlo + g);
    }
    __syncthreads();

    float acc[2][4][4];
    #pragma unroll
    for (int i = 0; i < 2; i++)
        #pragma unroll
        for (int j = 0; j < 4; j++)
            #pragma unroll
            for (int k = 0; k < 4; k++) acc[i][j][k] = 0.0f;

    #pragma unroll
    for (int ks = 0; ks < 4; ks++) {
        const int kr = ks * 16;
        unsigned qh[2][4], ql[2][4];
        #pragma unroll
        for (int mi = 0; mi < 2; mi++) {
            int m = wm * 32 + mi * 16 + (lane & 15);
            int kk = kr + (lane >> 4) * 8;
            ldsm4(qh[mi][0], qh[mi][1], qh[mi][2], qh[mi][3],
                  sb + QT_QH + (m * ALD + kk) * 2);
            ldsm4(ql[mi][0], ql[mi][1], ql[mi][2], ql[mi][3],
                  sb + QT_QL + (m * ALD + kk) * 2);
        }
        int kk2 = kr + (lane & 7) + ((lane >> 3) & 1) * 8;
        unsigned th[2][4], tl[2][4];
        #pragma unroll
        for (int no2 = 0; no2 < 2; no2++) {
            int n = wn * 32 + no2 * 16 + (lane >> 4) * 8;
            ldsm4t(th[no2][0], th[no2][1], th[no2][2], th[no2][3],
                   sb + QT_TH + (kk2 * ALD + n) * 2);
            ldsm4t(tl[no2][0], tl[no2][1], tl[no2][2], tl[no2][3],
                   sb + QT_TL + (kk2 * ALD + n) * 2);
        }
        #pragma unroll
        for (int mi = 0; mi < 2; mi++)
            #pragma unroll
            for (int no = 0; no < 4; no++) {
                unsigned* bhp = &th[no >> 1][(no & 1) * 2];
                unsigned* blp = &tl[no >> 1][(no & 1) * 2];
                mma_bf16(acc[mi][no], qh[mi], bhp[0], bhp[1]);
                mma_bf16(acc[mi][no], qh[mi], blp[0], blp[1]);
                mma_bf16(acc[mi][no], ql[mi], bhp[0], bhp[1]);
            }
    }

    __syncthreads();   // done reading Q smem before O overlay
    float* sO = reinterpret_cast<float*>(smq + QT_O);
    #pragma unroll
    for (int mi = 0; mi < 2; mi++)
        #pragma unroll
        for (int no = 0; no < 4; no++) {
            int row = wm * 32 + mi * 16 + (lane >> 2);
            int col = wn * 32 + no * 8 + (lane & 3) * 2;
            *reinterpret_cast<float2*>(&sO[row * OLD + col]) =
                make_float2(acc[mi][no][0], acc[mi][no][1]);
            *reinterpret_cast<float2*>(&sO[(row + 8) * OLD + col]) =
                make_float2(acc[mi][no][2], acc[mi][no][3]);
        }
    __syncthreads();

    // softmax over dk=64; 8 warps x 16 rows
    #pragma unroll
    for (int i = 0; i < 16; i++) {
        int r = wid * 16 + i;
        float v0 = sO[r * OLD + lane];
        float v1 = sO[r * OLD + lane + 32];
        float mx = fmaxf(v0, v1);
        #pragma unroll
        for (int o = 16; o > 0; o >>= 1)
            mx = fmaxf(mx, __shfl_xor_sync(0xffffffffu, mx, o));
        float e0 = __expf(v0 - mx), e1 = __expf(v1 - mx);
        float s = e0 + e1;
        #pragma unroll
        for (int o = 16; o > 0; o >>= 1) s += __shfl_xor_sync(0xffffffffu, s, o);
        float inv = 1.0f / s;
        float q0 = e0 * inv, q1 = e1 * inv;
        size_t g = base + (size_t)(s0 + r) * DK;
        bf16 h0 = __float2bfloat16(q0), h1 = __float2bfloat16(q1);
        Mhi[g + lane]      = h0;
        Mhi[g + lane + 32] = h1;
        Mlo[g + lane]      = __float2bfloat16(q0 - __bfloat162float(h0));
        Mlo[g + lane + 32] = __float2bfloat16(q1 - __bfloat162float(h1));
    }
}

// ===========================================================================
// Launch
// ===========================================================================
extern "C" void kernel_launch(void* const* d_in, const int* in_sizes, int n_in,
                              void* d_out, int out_size)
{
    const float* x  = (const float*)d_in[0];
    const float* Wq = (const float*)d_in[1];
    const float* bq = (const float*)d_in[2];
    const float* Wk = (const float*)d_in[3];
    const float* bk = (const float*)d_in[4];
    const float* Wv = (const float*)d_in[5];
    const float* bv = (const float*)d_in[6];
    const float* Wo = (const float*)d_in[7];
    const float* bo = (const float*)d_in[8];
    const float* Wf = (const float*)d_in[9];
    const float* bf_ = (const float*)d_in[10];
    float* out = (float*)d_out;

    bf16 *xhi, *xlo, *Whi, *Wlo, *WoThi, *WoTlo, *Wchi, *Wclo;
    bf16 *Qhi, *Qlo, *Khi, *Klo, *Vhi, *Vlo, *Mhi, *Mlo;
    float *bp, *zb, *Tp;
    cudaGetSymbolAddress((void**)&xhi, g_xhi); cudaGetSymbolAddress((void**)&xlo, g_xlo);
    cudaGetSymbolAddress((void**)&Whi, g_Whi); cudaGetSymbolAddress((void**)&Wlo, g_Wlo);
    cudaGetSymbolAddress((void**)&WoThi, g_WoThi); cudaGetSymbolAddress((void**)&WoTlo, g_WoTlo);
    cudaGetSymbolAddress((void**)&Wchi, g_Wchi); cudaGetSymbolAddress((void**)&Wclo, g_Wclo);
    cudaGetSymbolAddress((void**)&Qhi, g_Qhi); cudaGetSymbolAddress((void**)&Qlo, g_Qlo);
    cudaGetSymbolAddress((void**)&Khi, g_Khi); cudaGetSymbolAddress((void**)&Klo, g_Klo);
    cudaGetSymbolAddress((void**)&Vhi, g_Vhi); cudaGetSymbolAddress((void**)&Vlo, g_Vlo);
    cudaGetSymbolAddress((void**)&Mhi, g_Mhi); cudaGetSymbolAddress((void**)&Mlo, g_Mlo);
    cudaGetSymbolAddress((void**)&bp, g_bp); cudaGetSymbolAddress((void**)&zb, g_zb);
    cudaGetSymbolAddress((void**)&Tp, g_Tp);

    cudaFuncSetAttribute(qkv_gemm, cudaFuncAttributeMaxDynamicSharedMemorySize, GEMM_SMEM);
    cudaFuncSetAttribute(gemm64, cudaFuncAttributeMaxDynamicSharedMemorySize, GEMM64_SMEM);
    cudaFuncSetAttribute(ktv_kernel, cudaFuncAttributeMaxDynamicSharedMemorySize, KTV_SMEM);
    cudaFuncSetAttribute(qt_softmax, cudaFuncAttributeMaxDynamicSharedMemorySize, QT_SMEM);

    // one prep launch: converts + Wo transpose + b'
    prep_all<<<NCVT + NTRB + NBPB, 256>>>(x, Wq, Wk, Wv, Wf, Wo, bo, bf_,
                                          xhi, xlo, Whi, Wlo, WoThi, WoTlo, bp);

    // QKV projections + Wc = Wf@Wo folded in as z=3
    dim3 qgrid(DM/64, MROWS/128, 4);
    qkv_gemm<<<qgrid, 256, GEMM_SMEM>>>(xhi, xlo, Whi, Wlo, WoThi, WoTlo,
                                        bq, bk, bv, zb,
                                        Qhi, Qlo, Khi, Klo, Vhi, Vlo,
                                        Wchi, Wclo);

    // partial T = K^T V per (head, split)
    dim3 kgrid(NSPLIT, NHEADS);        // (4, 24)
    ktv_kernel<<<kgrid, 256, KTV_SMEM>>>(Khi, Klo, Vhi, Vlo, Tp);

    // O = Q (SCALE T), softmax -> M hi/lo
    dim3 sgrid(SEQ/128, NHEADS);       // (16, 24)
    qt_softmax<<<sgrid, 256, QT_SMEM>>>(Qhi, Qlo, Tp, Mhi, Mlo);

    // final projection: out = M @ Wc^T + b'
    dim3 ggrid(DM/64, MROWS/64);       // (12, 64)
    gemm64<<<ggrid, 128, GEMM64_SMEM>>>(Mhi, Mlo, Wchi, Wclo, bp, out);
}